// round 13
// baseline (speedup 1.0000x reference)
#include <cuda_runtime.h>
#include <cuda_bf16.h>
#include <cstdint>
#include <math.h>

#define N_NODES 50000
#define N_EDGES 800000
#define H 128
#define LAYERS 4
#define KE 263
#define KN 256
#define BM 128
#define KE_PAD 288

// edge + node shared smem layout (bytes), total 73728 (72KB) -> 3 CTAs/SM
#define ACTS_OFF  1024
#define ABUF0_OFF 35840
#define ABUF1_OFF 46080
#define BBUF0_OFF 56320
#define BBUF1_OFF 65024
#define SMEM_EDGE 73728

#define NACTS_OFF  1024
#define NABUF0_OFF 35840
#define NABUF1_OFF 46080
#define NBBUF0_OFF 56320
#define NBBUF1_OFF 65024
#define SMEM_NODE  73728
#define NLN_OFF    1024

__device__ float g_h[N_NODES * H];
__device__ float g_agg[N_NODES * H];
__device__ float g_ea[N_EDGES * 4];
__device__ __nv_bfloat16 g_hb[N_NODES * H];
__device__ __nv_bfloat16 g_aggb[N_NODES * H];
__device__ __nv_bfloat16 g_We1b[LAYERS * KE_PAD * H];
__device__ __nv_bfloat16 g_We2b[LAYERS * H * H];
__device__ __nv_bfloat16 g_We3b[LAYERS * H * H];
__device__ __nv_bfloat16 g_Wn1b[LAYERS * KN * H];
__device__ __nv_bfloat16 g_Wn2b[LAYERS * H * H];
__device__ __nv_bfloat16 g_Wn3b[LAYERS * H * H];

#define CP_COMMIT asm volatile("cp.async.commit_group;" ::: "memory")
#define CP_WAIT1  asm volatile("cp.async.wait_group 1;" ::: "memory")
#define CP_WAIT0  asm volatile("cp.async.wait_group 0;" ::: "memory")

__device__ __forceinline__ void cp16x2(unsigned dst, const void* src) {
    asm volatile("cp.async.cg.shared.global [%0], [%1], 16;\n\t"
                 "cp.async.cg.shared.global [%2], [%3], 16;"
                 :: "r"(dst), "l"(src), "r"(dst + 16), "l"((const char*)src + 16) : "memory");
}
__device__ __forceinline__ void red_add_f4(float* p, float a, float b, float c, float d) {
    asm volatile("red.global.add.v4.f32 [%0], {%1,%2,%3,%4};"
                 :: "l"(p), "f"(a), "f"(b), "f"(c), "f"(d) : "memory");
}
__device__ __forceinline__ unsigned pack_bf2(float lo, float hi) {
    __nv_bfloat162 v = __floats2bfloat162_rn(lo, hi);
    return *(unsigned*)&v;
}
__device__ __forceinline__ void ldsm_x4(unsigned& r0, unsigned& r1, unsigned& r2, unsigned& r3,
                                        unsigned addr) {
    asm volatile("ldmatrix.sync.aligned.m8n8.x4.shared.b16 {%0,%1,%2,%3}, [%4];"
                 : "=r"(r0), "=r"(r1), "=r"(r2), "=r"(r3) : "r"(addr));
}
__device__ __forceinline__ void ldsm_x4t(unsigned& r0, unsigned& r1, unsigned& r2, unsigned& r3,
                                         unsigned addr) {
    asm volatile("ldmatrix.sync.aligned.m8n8.x4.trans.shared.b16 {%0,%1,%2,%3}, [%4];"
                 : "=r"(r0), "=r"(r1), "=r"(r2), "=r"(r3) : "r"(addr));
}
__device__ __forceinline__ void mma_bf16(float d[4], const unsigned a[4], const unsigned b[2]) {
    asm volatile("mma.sync.aligned.m16n8k16.row.col.f32.bf16.bf16.f32 "
                 "{%0,%1,%2,%3}, {%4,%5,%6,%7}, {%8,%9}, {%0,%1,%2,%3};"
                 : "+f"(d[0]), "+f"(d[1]), "+f"(d[2]), "+f"(d[3])
                 : "r"(a[0]), "r"(a[1]), "r"(a[2]), "r"(a[3]), "r"(b[0]), "r"(b[1]));
}

// ---------------------------------------------------------------- weight prep (fp32 -> bf16)
__global__ void prep_weights(const float* __restrict__ We1,
                             const float* __restrict__ We2,
                             const float* __restrict__ We3,
                             const float* __restrict__ Wn1,
                             const float* __restrict__ Wn2,
                             const float* __restrict__ Wn3) {
    int id = blockIdx.x * blockDim.x + threadIdx.x;
    const int n1 = LAYERS * KE_PAD * H;
    const int n2 = LAYERS * H * H;
    const int n3 = LAYERS * KN * H;
    if (id < n1) {
        int l = id / (KE_PAD * H);
        int rem = id % (KE_PAD * H);
        int r = rem / H, c = rem % H;
        float v = (r < KE) ? We1[((size_t)l * KE + r) * H + c] : 0.f;
        g_We1b[id] = __float2bfloat16(v);
    } else if (id < n1 + n2) {
        g_We2b[id - n1] = __float2bfloat16(We2[id - n1]);
    } else if (id < n1 + 2 * n2) {
        g_We3b[id - n1 - n2] = __float2bfloat16(We3[id - n1 - n2]);
    } else if (id < n1 + 2 * n2 + n3) {
        int k = id - n1 - 2 * n2;
        g_Wn1b[k] = __float2bfloat16(Wn1[k]);
    } else if (id < n1 + 2 * n2 + n3 + n2) {
        int k = id - n1 - 2 * n2 - n3;
        g_Wn2b[k] = __float2bfloat16(Wn2[k]);
    } else if (id < n1 + 2 * n2 + n3 + 2 * n2) {
        int k = id - n1 - 2 * n2 - n3 - n2;
        g_Wn3b[k] = __float2bfloat16(Wn3[k]);
    }
}

// ---------------------------------------------------------------- embed (+ zero g_agg)
__global__ void embed_kernel(const float* __restrict__ x,
                             const float* __restrict__ W,
                             const float* __restrict__ b) {
    int gid = blockIdx.x * blockDim.x + threadIdx.x;
    if (gid >= N_NODES * H) return;
    int i = gid >> 7;
    int j = gid & (H - 1);
    const float* xr = x + i * 16;
    float acc = b[j];
#pragma unroll
    for (int k = 0; k < 16; k++) acc += xr[k] * W[k * H + j];
    g_h[gid] = acc;
    g_hb[gid] = __float2bfloat16(acc);
    g_agg[gid] = 0.f;
}

__global__ void ea_kernel(const float* __restrict__ pos,
                          const int* __restrict__ rowIdx,
                          const int* __restrict__ colIdx) {
    int e = blockIdx.x * blockDim.x + threadIdx.x;
    if (e >= N_EDGES) return;
    int r = rowIdx[e], c = colIdx[e];
    float dx = pos[c * 3 + 0] - pos[r * 3 + 0];
    float dy = pos[c * 3 + 1] - pos[r * 3 + 1];
    float dz = pos[c * 3 + 2] - pos[r * 3 + 2];
    float d = sqrtf(dx * dx + dy * dy + dz * dz);
    *(float4*)&g_ea[e * 4] = make_float4(dx, dy, dz, d);
}

// convert agg -> bf16 mirror, then re-zero agg for the next layer
__global__ void cvt_agg_kernel() {
    int gid = blockIdx.x * blockDim.x + threadIdx.x;
    float4* src = (float4*)g_agg;
    float4 a = src[2 * gid];
    float4 b = src[2 * gid + 1];
    uint4 o;
    o.x = pack_bf2(a.x, a.y);
    o.y = pack_bf2(a.z, a.w);
    o.z = pack_bf2(b.x, b.y);
    o.w = pack_bf2(b.z, b.w);
    ((uint4*)g_aggb)[gid] = o;
    float4 z = make_float4(0.f, 0.f, 0.f, 0.f);
    src[2 * gid] = z;
    src[2 * gid + 1] = z;
}

// ---------------------------------------------------------------- fused edge MLP
__global__ __launch_bounds__(256, 3)
void edge_kernel(int layer,
                 const float* __restrict__ be1, const float* __restrict__ be2,
                 const float* __restrict__ be3,
                 const int* __restrict__ rowIdx, const int* __restrict__ colIdx) {
    extern __shared__ __align__(16) unsigned smem_u[];
    int* s_col = (int*)smem_u;
    int* s_row = s_col + 128;
    unsigned* sActs = smem_u + ACTS_OFF / 4;
    unsigned* sA8 = smem_u + ACTS_OFF / 4;    // ea-tail tile aliases acts start

    unsigned sbase;
    asm("{ .reg .u64 t; cvta.to.shared.u64 t, %1; cvt.u32.u64 %0, t; }"
        : "=r"(sbase) : "l"(smem_u));
    const unsigned actsB = sbase + ACTS_OFF;
    const unsigned a8B = actsB;
    const unsigned abufB[2] = {sbase + ABUF0_OFF, sbase + ABUF1_OFF};
    const unsigned bbufB[2] = {sbase + BBUF0_OFF, sbase + BBUF1_OFF};

    const __nv_bfloat16* W1 = &g_We1b[(size_t)layer * KE_PAD * H];
    const __nv_bfloat16* W2 = &g_We2b[(size_t)layer * H * H];
    const __nv_bfloat16* W3 = &g_We3b[(size_t)layer * H * H];

    int tid = threadIdx.x;
    int eb = blockIdx.x * BM;

    if (tid < 128) s_col[tid] = colIdx[eb + tid];
    else           s_row[tid - 128] = rowIdx[eb + tid - 128];
    __syncthreads();

    int warp = tid >> 5, lane = tid & 31;
    int lr = lane >> 2, lc = lane & 3;
    int wm = (warp & 1) * 64;
    int wn = (warp >> 1) * 32;

    int rA = tid >> 1, halfA = tid & 1;
    int rB = tid >> 3;
    int cB = (tid & 7) * 16;

    // ea-tail tile (ea + rel_mom), pitch 48B, at acts start (read only during GEMM1)
    if (tid < 128) {
        int r = tid;
        float4 ea = *(const float4*)&g_ea[(eb + r) * 4];
        int ci = s_col[r] * H, ri = s_row[r] * H;
        float rm0 = g_h[ci + 3] - g_h[ri + 3];
        float rm1 = g_h[ci + 4] - g_h[ri + 4];
        float rm2 = g_h[ci + 5] - g_h[ri + 5];
        unsigned* dst = &sA8[r * 12];
        dst[0] = pack_bf2(ea.x, ea.y);
        dst[1] = pack_bf2(ea.z, ea.w);
        dst[2] = pack_bf2(rm0, rm1);
        dst[3] = pack_bf2(rm2, 0.f);
        dst[4] = 0u; dst[5] = 0u; dst[6] = 0u; dst[7] = 0u;
    }

    float d[4][4][4];
#pragma unroll
    for (int mt = 0; mt < 4; mt++)
#pragma unroll
        for (int nt = 0; nt < 4; nt++)
#pragma unroll
            for (int i = 0; i < 4; i++) d[mt][nt][i] = 0.f;

    auto issueA = [&](int ch, int p) {
        int node = (ch < 4) ? s_col[rA] : s_row[rA];
        int kbase = (ch & 3) * 32;
        cp16x2(abufB[p] + rA * 80 + halfA * 32,
               &g_hb[(size_t)node * H + kbase + halfA * 16]);
    };
    auto issueB = [&](const __nv_bfloat16* Wb, int ch, int p) {
        cp16x2(bbufB[p] + rB * 272 + cB * 2,
               &Wb[(size_t)(ch * 32 + rB) * H + cB]);
    };

    // ===== GEMM1: K = 288 padded (9 chunks, double-buffered)
    issueA(0, 0);
    issueB(W1, 0, 0);
    CP_COMMIT;

    for (int ch = 0; ch <= 8; ch++) {
        int p = ch & 1;
        if (ch < 8) {
            int p1 = (ch + 1) & 1;
            if (ch + 1 < 8) issueA(ch + 1, p1);
            issueB(W1, ch + 1, p1);
            CP_COMMIT;
            CP_WAIT1;
        } else {
            CP_WAIT0;
        }
        __syncthreads();
        int nk16 = (ch < 8) ? 2 : 1;
        for (int k16 = 0; k16 < nk16; k16++) {
            int k0 = k16 * 16;
            unsigned a[4][4], b[4][2];
            if (ch < 8) {
#pragma unroll
                for (int mt = 0; mt < 4; mt++)
                    ldsm_x4(a[mt][0], a[mt][1], a[mt][2], a[mt][3],
                            abufB[p] + (wm + mt * 16 + (lane & 15)) * 80
                                     + (k0 + ((lane >> 4) << 3)) * 2);
            } else {
#pragma unroll
                for (int mt = 0; mt < 4; mt++)
                    ldsm_x4(a[mt][0], a[mt][1], a[mt][2], a[mt][3],
                            a8B + (wm + mt * 16 + (lane & 15)) * 48
                                + ((lane >> 4) << 3) * 2);
            }
#pragma unroll
            for (int np = 0; np < 2; np++)
                ldsm_x4t(b[2 * np][0], b[2 * np][1], b[2 * np + 1][0], b[2 * np + 1][1],
                         bbufB[p] + (k0 + (lane & 7) + (lane & 8)) * 272
                                  + (wn + np * 16 + ((lane >> 4) << 3)) * 2);
#pragma unroll
            for (int mt = 0; mt < 4; mt++)
#pragma unroll
                for (int nt = 0; nt < 4; nt++) mma_bf16(d[mt][nt], a[mt], b[nt]);
        }
        __syncthreads();
    }

    issueB(W2, 0, 0);
    CP_COMMIT;

    // epilogue1: bias + relu -> acts
#pragma unroll
    for (int mt = 0; mt < 4; mt++)
#pragma unroll
        for (int nt = 0; nt < 4; nt++) {
            int row = wm + mt * 16 + lr;
            int col = wn + nt * 8 + 2 * lc;
            float2 bv = *(const float2*)&be1[col];
            sActs[(row * 136 + col) >> 1] =
                pack_bf2(fmaxf(d[mt][nt][0] + bv.x, 0.f), fmaxf(d[mt][nt][1] + bv.y, 0.f));
            sActs[((row + 8) * 136 + col) >> 1] =
                pack_bf2(fmaxf(d[mt][nt][2] + bv.x, 0.f), fmaxf(d[mt][nt][3] + bv.y, 0.f));
        }

    // ===== GEMM2
#pragma unroll
    for (int mt = 0; mt < 4; mt++)
#pragma unroll
        for (int nt = 0; nt < 4; nt++)
#pragma unroll
            for (int i = 0; i < 4; i++) d[mt][nt][i] = 0.f;

    for (int ch = 0; ch < 4; ch++) {
        int p = ch & 1;
        if (ch < 3) {
            issueB(W2, ch + 1, (ch + 1) & 1);
            CP_COMMIT;
            CP_WAIT1;
        } else {
            CP_WAIT0;
        }
        __syncthreads();
#pragma unroll
        for (int k16 = 0; k16 < 2; k16++) {
            int kg = ch * 32 + k16 * 16;
            int k0 = k16 * 16;
            unsigned a[4][4], b[4][2];
#pragma unroll
            for (int mt = 0; mt < 4; mt++)
                ldsm_x4(a[mt][0], a[mt][1], a[mt][2], a[mt][3],
                        actsB + (wm + mt * 16 + (lane & 15)) * 272
                              + (kg + ((lane >> 4) << 3)) * 2);
#pragma unroll
            for (int np = 0; np < 2; np++)
                ldsm_x4t(b[2 * np][0], b[2 * np][1], b[2 * np + 1][0], b[2 * np + 1][1],
                         bbufB[p] + (k0 + (lane & 7) + (lane & 8)) * 272
                                  + (wn + np * 16 + ((lane >> 4) << 3)) * 2);
#pragma unroll
            for (int mt = 0; mt < 4; mt++)
#pragma unroll
                for (int nt = 0; nt < 4; nt++) mma_bf16(d[mt][nt], a[mt], b[nt]);
        }
        __syncthreads();
    }

    issueB(W3, 0, 0);
    CP_COMMIT;

#pragma unroll
    for (int mt = 0; mt < 4; mt++)
#pragma unroll
        for (int nt = 0; nt < 4; nt++) {
            int row = wm + mt * 16 + lr;
            int col = wn + nt * 8 + 2 * lc;
            float2 bv = *(const float2*)&be2[col];
            sActs[(row * 136 + col) >> 1] =
                pack_bf2(fmaxf(d[mt][nt][0] + bv.x, 0.f), fmaxf(d[mt][nt][1] + bv.y, 0.f));
            sActs[((row + 8) * 136 + col) >> 1] =
                pack_bf2(fmaxf(d[mt][nt][2] + bv.x, 0.f), fmaxf(d[mt][nt][3] + bv.y, 0.f));
        }

    // ===== GEMM3
#pragma unroll
    for (int mt = 0; mt < 4; mt++)
#pragma unroll
        for (int nt = 0; nt < 4; nt++)
#pragma unroll
            for (int i = 0; i < 4; i++) d[mt][nt][i] = 0.f;

    for (int ch = 0; ch < 4; ch++) {
        int p = ch & 1;
        if (ch < 3) {
            issueB(W3, ch + 1, (ch + 1) & 1);
            CP_COMMIT;
            CP_WAIT1;
        } else {
            CP_WAIT0;
        }
        __syncthreads();
#pragma unroll
        for (int k16 = 0; k16 < 2; k16++) {
            int kg = ch * 32 + k16 * 16;
            int k0 = k16 * 16;
            unsigned a[4][4], b[4][2];
#pragma unroll
            for (int mt = 0; mt < 4; mt++)
                ldsm_x4(a[mt][0], a[mt][1], a[mt][2], a[mt][3],
                        actsB + (wm + mt * 16 + (lane & 15)) * 272
                              + (kg + ((lane >> 4) << 3)) * 2);
#pragma unroll
            for (int np = 0; np < 2; np++)
                ldsm_x4t(b[2 * np][0], b[2 * np][1], b[2 * np + 1][0], b[2 * np + 1][1],
                         bbufB[p] + (k0 + (lane & 7) + (lane & 8)) * 272
                                  + (wn + np * 16 + ((lane >> 4) << 3)) * 2);
#pragma unroll
            for (int mt = 0; mt < 4; mt++)
#pragma unroll
                for (int nt = 0; nt < 4; nt++) mma_bf16(d[mt][nt], a[mt], b[nt]);
        }
        __syncthreads();
    }

    // epilogue3: pair-shuffle v4 reds
#pragma unroll
    for (int mt = 0; mt < 4; mt++)
#pragma unroll
        for (int nt = 0; nt < 4; nt++) {
            int colseg = wn + nt * 8 + ((lc & 2) << 1);
            float4 bv = *(const float4*)&be3[colseg];
            bool ev = (lc & 1) == 0;
            float s0 = ev ? d[mt][nt][2] : d[mt][nt][0];
            float s1 = ev ? d[mt][nt][3] : d[mt][nt][1];
            float r0 = __uint_as_float(__shfl_xor_sync(0xffffffffu, __float_as_uint(s0), 1));
            float r1 = __uint_as_float(__shfl_xor_sync(0xffffffffu, __float_as_uint(s1), 1));
            int e0 = wm + mt * 16 + lr;
            if (ev) {
                int tgt = s_col[e0];
                red_add_f4(&g_agg[(size_t)tgt * H + colseg],
                           d[mt][nt][0] + bv.x, d[mt][nt][1] + bv.y,
                           r0 + bv.z, r1 + bv.w);
            } else {
                int tgt = s_col[e0 + 8];
                red_add_f4(&g_agg[(size_t)tgt * H + colseg],
                           r0 + bv.x, r1 + bv.y,
                           d[mt][nt][2] + bv.z, d[mt][nt][3] + bv.w);
            }
        }
}

// ---------------------------------------------------------------- node MLP
__global__ __launch_bounds__(256, 3)
void node_kernel(int layer,
                 const float* __restrict__ bn1, const float* __restrict__ bn2,
                 const float* __restrict__ bn3,
                 const float* __restrict__ lng, const float* __restrict__ lnb,
                 float* __restrict__ out) {
    extern __shared__ __align__(16) unsigned smem_u[];
    unsigned* sActs = smem_u + NACTS_OFF / 4;
    float* sLN = (float*)(smem_u + NLN_OFF / 4);

    unsigned sbase;
    asm("{ .reg .u64 t; cvta.to.shared.u64 t, %1; cvt.u32.u64 %0, t; }"
        : "=r"(sbase) : "l"(smem_u));
    const unsigned actsB = sbase + NACTS_OFF;
    const unsigned abufB[2] = {sbase + NABUF0_OFF, sbase + NABUF1_OFF};
    const unsigned bbufB[2] = {sbase + NBBUF0_OFF, sbase + NBBUF1_OFF};

    const __nv_bfloat16* W1 = &g_Wn1b[(size_t)layer * KN * H];
    const __nv_bfloat16* W2 = &g_Wn2b[(size_t)layer * H * H];
    const __nv_bfloat16* W3 = &g_Wn3b[(size_t)layer * H * H];

    int tid = threadIdx.x;
    int nb = blockIdx.x * BM;

    int warp = tid >> 5, lane = tid & 31;
    int lr = lane >> 2, lc = lane & 3;
    int wm = (warp & 1) * 64;
    int wn = (warp >> 1) * 32;

    int rA = tid >> 1, halfA = tid & 1;
    int rB = tid >> 3;
    int cB = (tid & 7) * 16;
    int nodeA = nb + rA; if (nodeA >= N_NODES) nodeA = N_NODES - 1;

    float d[4][4][4];
#pragma unroll
    for (int mt = 0; mt < 4; mt++)
#pragma unroll
        for (int nt = 0; nt < 4; nt++)
#pragma unroll
            for (int i = 0; i < 4; i++) d[mt][nt][i] = 0.f;

    auto issueA = [&](int ch, int p) {
        const __nv_bfloat16* src = (ch < 4)
            ? &g_hb[(size_t)nodeA * H + ch * 32 + halfA * 16]
            : &g_aggb[(size_t)nodeA * H + (ch - 4) * 32 + halfA * 16];
        cp16x2(abufB[p] + rA * 80 + halfA * 32, src);
    };
    auto issueB = [&](const __nv_bfloat16* Wb, int ch, int p) {
        cp16x2(bbufB[p] + rB * 272 + cB * 2,
               &Wb[(size_t)(ch * 32 + rB) * H + cB]);
    };

    issueA(0, 0);
    issueB(W1, 0, 0);
    CP_COMMIT;

    for (int ch = 0; ch < 8; ch++) {
        int p = ch & 1;
        if (ch < 7) {
            int p1 = (ch + 1) & 1;
            issueA(ch + 1, p1);
            issueB(W1, ch + 1, p1);
            CP_COMMIT;
            CP_WAIT1;
        } else {
            CP_WAIT0;
        }
        __syncthreads();
#pragma unroll
        for (int k16 = 0; k16 < 2; k16++) {
            int k0 = k16 * 16;
            unsigned a[4][4], b[4][2];
#pragma unroll
            for (int mt = 0; mt < 4; mt++)
                ldsm_x4(a[mt][0], a[mt][1], a[mt][2], a[mt][3],
                        abufB[p] + (wm + mt * 16 + (lane & 15)) * 80
                                 + (k0 + ((lane >> 4) << 3)) * 2);
#pragma unroll
            for (int np = 0; np < 2; np++)
                ldsm_x4t(b[2 * np][0], b[2 * np][1], b[2 * np + 1][0], b[2 * np + 1][1],
                         bbufB[p] + (k0 + (lane & 7) + (lane & 8)) * 272
                                  + (wn + np * 16 + ((lane >> 4) << 3)) * 2);
#pragma unroll
            for (int mt = 0; mt < 4; mt++)
#pragma unroll
                for (int nt = 0; nt < 4; nt++) mma_bf16(d[mt][nt], a[mt], b[nt]);
        }
        __syncthreads();
    }

    issueB(W2, 0, 0);
    CP_COMMIT;

#pragma unroll
    for (int mt = 0; mt < 4; mt++)
#pragma unroll
        for (int nt = 0; nt < 4; nt++) {
            int row = wm + mt * 16 + lr;
            int col = wn + nt * 8 + 2 * lc;
            float2 bv = *(const float2*)&bn1[col];
            sActs[(row * 136 + col) >> 1] =
                pack_bf2(fmaxf(d[mt][nt][0] + bv.x, 0.f), fmaxf(d[mt][nt][1] + bv.y, 0.f));
            sActs[((row + 8) * 136 + col) >> 1] =
                pack_bf2(fmaxf(d[mt][nt][2] + bv.x, 0.f), fmaxf(d[mt][nt][3] + bv.y, 0.f));
        }

#pragma unroll
    for (int mt = 0; mt < 4; mt++)
#pragma unroll
        for (int nt = 0; nt < 4; nt++)
#pragma unroll
            for (int i = 0; i < 4; i++) d[mt][nt][i] = 0.f;

    for (int ch = 0; ch < 4; ch++) {
        int p = ch & 1;
        if (ch < 3) {
            issueB(W2, ch + 1, (ch + 1) & 1);
            CP_COMMIT;
            CP_WAIT1;
        } else {
            CP_WAIT0;
        }
        __syncthreads();
#pragma unroll
        for (int k16 = 0; k16 < 2; k16++) {
            int kg = ch * 32 + k16 * 16;
            int k0 = k16 * 16;
            unsigned a[4][4], b[4][2];
#pragma unroll
            for (int mt = 0; mt < 4; mt++)
                ldsm_x4(a[mt][0], a[mt][1], a[mt][2], a[mt][3],
                        actsB + (wm + mt * 16 + (lane & 15)) * 272
                              + (kg + ((lane >> 4) << 3)) * 2);
#pragma unroll
            for (int np = 0; np < 2; np++)
                ldsm_x4t(b[2 * np][0], b[2 * np][1], b[2 * np + 1][0], b[2 * np + 1][1],
                         bbufB[p] + (k0 + (lane & 7) + (lane & 8)) * 272
                                  + (wn + np * 16 + ((lane >> 4) << 3)) * 2);
#pragma unroll
            for (int mt = 0; mt < 4; mt++)
#pragma unroll
                for (int nt = 0; nt < 4; nt++) mma_bf16(d[mt][nt], a[mt], b[nt]);
        }
        __syncthreads();
    }

    issueB(W3, 0, 0);
    CP_COMMIT;

#pragma unroll
    for (int mt = 0; mt < 4; mt++)
#pragma unroll
        for (int nt = 0; nt < 4; nt++) {
            int row = wm + mt * 16 + lr;
            int col = wn + nt * 8 + 2 * lc;
            float2 bv = *(const float2*)&bn2[col];
            sActs[(row * 136 + col) >> 1] =
                pack_bf2(fmaxf(d[mt][nt][0] + bv.x, 0.f), fmaxf(d[mt][nt][1] + bv.y, 0.f));
            sActs[((row + 8) * 136 + col) >> 1] =
                pack_bf2(fmaxf(d[mt][nt][2] + bv.x, 0.f), fmaxf(d[mt][nt][3] + bv.y, 0.f));
        }

#pragma unroll
    for (int mt = 0; mt < 4; mt++)
#pragma unroll
        for (int nt = 0; nt < 4; nt++)
#pragma unroll
            for (int i = 0; i < 4; i++) d[mt][nt][i] = 0.f;

    for (int ch = 0; ch < 4; ch++) {
        int p = ch & 1;
        if (ch < 3) {
            issueB(W3, ch + 1, (ch + 1) & 1);
            CP_COMMIT;
            CP_WAIT1;
        } else {
            CP_WAIT0;
        }
        __syncthreads();
#pragma unroll
        for (int k16 = 0; k16 < 2; k16++) {
            int kg = ch * 32 + k16 * 16;
            int k0 = k16 * 16;
            unsigned a[4][4], b[4][2];
#pragma unroll
            for (int mt = 0; mt < 4; mt++)
                ldsm_x4(a[mt][0], a[mt][1], a[mt][2], a[mt][3],
                        actsB + (wm + mt * 16 + (lane & 15)) * 272
                              + (kg + ((lane >> 4) << 3)) * 2);
#pragma unroll
            for (int np = 0; np < 2; np++)
                ldsm_x4t(b[2 * np][0], b[2 * np][1], b[2 * np + 1][0], b[2 * np + 1][1],
                         bbufB[p] + (k0 + (lane & 7) + (lane & 8)) * 272
                                  + (wn + np * 16 + ((lane >> 4) << 3)) * 2);
#pragma unroll
            for (int mt = 0; mt < 4; mt++)
#pragma unroll
                for (int nt = 0; nt < 4; nt++) mma_bf16(d[mt][nt], a[mt], b[nt]);
        }
        __syncthreads();
    }

#pragma unroll
    for (int mt = 0; mt < 4; mt++)
#pragma unroll
        for (int nt = 0; nt < 4; nt++) {
            int row = wm + mt * 16 + lr;
            int col = wn + nt * 8 + 2 * lc;
            float2 bv = *(const float2*)&bn3[col];
            int n0 = nb + row, n1 = nb + row + 8;
            float2 h0 = make_float2(0.f, 0.f), h1 = make_float2(0.f, 0.f);
            if (n0 < N_NODES) h0 = *(const float2*)&g_h[n0 * H + col];
            if (n1 < N_NODES) h1 = *(const float2*)&g_h[n1 * H + col];
            *(float2*)&sLN[row * 132 + col] =
                make_float2(h0.x + d[mt][nt][0] + bv.x, h0.y + d[mt][nt][1] + bv.y);
            *(float2*)&sLN[(row + 8) * 132 + col] =
                make_float2(h1.x + d[mt][nt][2] + bv.x, h1.y + d[mt][nt][3] + bv.y);
        }
    __syncthreads();

    {
        for (int r = warp * 16; r < warp * 16 + 16; r++) {
            int node = nb + r;
            float v0 = sLN[r * 132 + lane];
            float v1 = sLN[r * 132 + lane + 32];
            float v2 = sLN[r * 132 + lane + 64];
            float v3 = sLN[r * 132 + lane + 96];
            float s = v0 + v1 + v2 + v3;
            float q = v0 * v0 + v1 * v1 + v2 * v2 + v3 * v3;
#pragma unroll
            for (int off = 16; off > 0; off >>= 1) {
                s += __shfl_xor_sync(0xffffffffu, s, off);
                q += __shfl_xor_sync(0xffffffffu, q, off);
            }
            float mean = s * (1.f / 128.f);
            float var = q * (1.f / 128.f) - mean * mean;
            float rstd = rsqrtf(var + 1e-5f);
            if (node < N_NODES) {
                float o0 = (v0 - mean) * rstd * lng[lane]      + lnb[lane];
                float o1 = (v1 - mean) * rstd * lng[lane + 32] + lnb[lane + 32];
                float o2 = (v2 - mean) * rstd * lng[lane + 64] + lnb[lane + 64];
                float o3 = (v3 - mean) * rstd * lng[lane + 96] + lnb[lane + 96];
                out[node * H + lane]      = o0;
                out[node * H + lane + 32] = o1;
                out[node * H + lane + 64] = o2;
                out[node * H + lane + 96] = o3;
                g_hb[node * H + lane]      = __float2bfloat16(o0);
                g_hb[node * H + lane + 32] = __float2bfloat16(o1);
                g_hb[node * H + lane + 64] = __float2bfloat16(o2);
                g_hb[node * H + lane + 96] = __float2bfloat16(o3);
            }
        }
    }
}

// ----------------------------------------------------------------
extern "C" void kernel_launch(void* const* d_in, const int* in_sizes, int n_in,
                              void* d_out, int out_size) {
    const float* x    = (const float*)d_in[0];
    const float* pos  = (const float*)d_in[1];
    const int*   ei   = (const int*)d_in[2];
    const float* W_in = (const float*)d_in[3];
    const float* b_in = (const float*)d_in[4];
    const float* We1  = (const float*)d_in[5];
    const float* be1  = (const float*)d_in[6];
    const float* We2  = (const float*)d_in[7];
    const float* be2  = (const float*)d_in[8];
    const float* We3  = (const float*)d_in[9];
    const float* be3  = (const float*)d_in[10];
    const float* Wn1  = (const float*)d_in[11];
    const float* bn1  = (const float*)d_in[12];
    const float* Wn2  = (const float*)d_in[13];
    const float* bn2  = (const float*)d_in[14];
    const float* Wn3  = (const float*)d_in[15];
    const float* bn3  = (const float*)d_in[16];
    const float* ln_g = (const float*)d_in[17];
    const float* ln_b = (const float*)d_in[18];

    const int* rowIdx = ei;
    const int* colIdx = ei + N_EDGES;

    cudaFuncSetAttribute(edge_kernel, cudaFuncAttributeMaxDynamicSharedMemorySize, SMEM_EDGE);
    cudaFuncSetAttribute(node_kernel, cudaFuncAttributeMaxDynamicSharedMemorySize, SMEM_NODE);
    // full shared-memory carveout so 3 CTAs/SM can be resident
    cudaFuncSetAttribute(edge_kernel, cudaFuncAttributePreferredSharedMemoryCarveout, 100);
    cudaFuncSetAttribute(node_kernel, cudaFuncAttributePreferredSharedMemoryCarveout, 100);

    float* hptr = nullptr;
    cudaGetSymbolAddress((void**)&hptr, g_h);

    int prep_total = LAYERS * KE_PAD * H + 2 * LAYERS * H * H
                   + LAYERS * KN * H + 2 * LAYERS * H * H;
    // launch order keeps edge_kernel at process-launch #4 (ncu capture slot)
    prep_weights<<<(prep_total + 255) / 256, 256>>>(We1, We2, We3, Wn1, Wn2, Wn3);
    embed_kernel<<<(N_NODES * H + 255) / 256, 256>>>(x, W_in, b_in);  // also zeroes g_agg
    ea_kernel<<<(N_EDGES + 255) / 256, 256>>>(pos, rowIdx, colIdx);

    int edge_blocks = N_EDGES / BM;
    int node_blocks = (N_NODES + BM - 1) / BM;
    int cvt_blocks = (N_NODES * H / 8) / 256;

    for (int l = 0; l < LAYERS; l++) {
        edge_kernel<<<edge_blocks, 256, SMEM_EDGE>>>(
            l, be1 + l * H, be2 + l * H, be3 + l * H, rowIdx, colIdx);
        cvt_agg_kernel<<<cvt_blocks, 256>>>();
        float* outp = (l == LAYERS - 1) ? (float*)d_out : hptr;
        node_kernel<<<node_blocks, 256, SMEM_NODE>>>(
            l, bn1 + l * H, bn2 + l * H, bn3 + l * H,
            ln_g + l * H, ln_b + l * H, outp);
    }
}

// round 14
// speedup vs baseline: 1.3799x; 1.3799x over previous
#include <cuda_runtime.h>
#include <cuda_bf16.h>
#include <cstdint>
#include <math.h>

#define N_NODES 50000
#define N_EDGES 800000
#define H 128
#define LAYERS 4
#define KE 263
#define KN 256
#define BM 128
#define KE_PAD 288

// edge + node shared smem layout (bytes), total 73728 (72KB) -> 3 CTAs/SM
#define ACTS_OFF  1024
#define ABUF0_OFF 35840
#define ABUF1_OFF 46080
#define BBUF0_OFF 56320
#define BBUF1_OFF 65024
#define SMEM_EDGE 73728

#define NACTS_OFF  1024
#define NABUF0_OFF 35840
#define NABUF1_OFF 46080
#define NBBUF0_OFF 56320
#define NBBUF1_OFF 65024
#define SMEM_NODE  73728
#define NLN_OFF    1024

__device__ float g_h[N_NODES * H];
__device__ float g_agg[N_NODES * H];
__device__ float g_ea[N_EDGES * 4];
__device__ __nv_bfloat16 g_hb[N_NODES * H];
__device__ __nv_bfloat16 g_aggb[N_NODES * H];
__device__ __nv_bfloat16 g_We1b[LAYERS * KE_PAD * H];
__device__ __nv_bfloat16 g_We2b[LAYERS * H * H];
__device__ __nv_bfloat16 g_We3b[LAYERS * H * H];
__device__ __nv_bfloat16 g_Wn1b[LAYERS * KN * H];
__device__ __nv_bfloat16 g_Wn2b[LAYERS * H * H];
__device__ __nv_bfloat16 g_Wn3b[LAYERS * H * H];

#define CP_COMMIT asm volatile("cp.async.commit_group;" ::: "memory")
#define CP_WAIT1  asm volatile("cp.async.wait_group 1;" ::: "memory")
#define CP_WAIT0  asm volatile("cp.async.wait_group 0;" ::: "memory")

__device__ __forceinline__ void cp16x2(unsigned dst, const void* src) {
    asm volatile("cp.async.cg.shared.global [%0], [%1], 16;\n\t"
                 "cp.async.cg.shared.global [%2], [%3], 16;"
                 :: "r"(dst), "l"(src), "r"(dst + 16), "l"((const char*)src + 16) : "memory");
}
__device__ __forceinline__ void red_add_f4(float* p, float a, float b, float c, float d) {
    asm volatile("red.global.add.v4.f32 [%0], {%1,%2,%3,%4};"
                 :: "l"(p), "f"(a), "f"(b), "f"(c), "f"(d) : "memory");
}
__device__ __forceinline__ unsigned pack_bf2(float lo, float hi) {
    __nv_bfloat162 v = __floats2bfloat162_rn(lo, hi);
    return *(unsigned*)&v;
}
__device__ __forceinline__ void ldsm_x4(unsigned& r0, unsigned& r1, unsigned& r2, unsigned& r3,
                                        unsigned addr) {
    asm volatile("ldmatrix.sync.aligned.m8n8.x4.shared.b16 {%0,%1,%2,%3}, [%4];"
                 : "=r"(r0), "=r"(r1), "=r"(r2), "=r"(r3) : "r"(addr));
}
__device__ __forceinline__ void ldsm_x4t(unsigned& r0, unsigned& r1, unsigned& r2, unsigned& r3,
                                         unsigned addr) {
    asm volatile("ldmatrix.sync.aligned.m8n8.x4.trans.shared.b16 {%0,%1,%2,%3}, [%4];"
                 : "=r"(r0), "=r"(r1), "=r"(r2), "=r"(r3) : "r"(addr));
}
__device__ __forceinline__ void mma_bf16(float d[4], const unsigned a[4], const unsigned b[2]) {
    asm volatile("mma.sync.aligned.m16n8k16.row.col.f32.bf16.bf16.f32 "
                 "{%0,%1,%2,%3}, {%4,%5,%6,%7}, {%8,%9}, {%0,%1,%2,%3};"
                 : "+f"(d[0]), "+f"(d[1]), "+f"(d[2]), "+f"(d[3])
                 : "r"(a[0]), "r"(a[1]), "r"(a[2]), "r"(a[3]), "r"(b[0]), "r"(b[1]));
}

// ---------------------------------------------------------------- weight prep (fp32 -> bf16)
__global__ void prep_weights(const float* __restrict__ We1,
                             const float* __restrict__ We2,
                             const float* __restrict__ We3,
                             const float* __restrict__ Wn1,
                             const float* __restrict__ Wn2,
                             const float* __restrict__ Wn3) {
    int id = blockIdx.x * blockDim.x + threadIdx.x;
    const int n1 = LAYERS * KE_PAD * H;
    const int n2 = LAYERS * H * H;
    const int n3 = LAYERS * KN * H;
    if (id < n1) {
        int l = id / (KE_PAD * H);
        int rem = id % (KE_PAD * H);
        int r = rem / H, c = rem % H;
        float v = (r < KE) ? We1[((size_t)l * KE + r) * H + c] : 0.f;
        g_We1b[id] = __float2bfloat16(v);
    } else if (id < n1 + n2) {
        g_We2b[id - n1] = __float2bfloat16(We2[id - n1]);
    } else if (id < n1 + 2 * n2) {
        g_We3b[id - n1 - n2] = __float2bfloat16(We3[id - n1 - n2]);
    } else if (id < n1 + 2 * n2 + n3) {
        int k = id - n1 - 2 * n2;
        g_Wn1b[k] = __float2bfloat16(Wn1[k]);
    } else if (id < n1 + 2 * n2 + n3 + n2) {
        int k = id - n1 - 2 * n2 - n3;
        g_Wn2b[k] = __float2bfloat16(Wn2[k]);
    } else if (id < n1 + 2 * n2 + n3 + 2 * n2) {
        int k = id - n1 - 2 * n2 - n3 - n2;
        g_Wn3b[k] = __float2bfloat16(Wn3[k]);
    }
}

// ---------------------------------------------------------------- embed (+ zero g_agg)
__global__ void embed_kernel(const float* __restrict__ x,
                             const float* __restrict__ W,
                             const float* __restrict__ b) {
    int gid = blockIdx.x * blockDim.x + threadIdx.x;
    if (gid >= N_NODES * H) return;
    int i = gid >> 7;
    int j = gid & (H - 1);
    const float* xr = x + i * 16;
    float acc = b[j];
#pragma unroll
    for (int k = 0; k < 16; k++) acc += xr[k] * W[k * H + j];
    g_h[gid] = acc;
    g_hb[gid] = __float2bfloat16(acc);
    g_agg[gid] = 0.f;
}

__global__ void ea_kernel(const float* __restrict__ pos,
                          const int* __restrict__ rowIdx,
                          const int* __restrict__ colIdx) {
    int e = blockIdx.x * blockDim.x + threadIdx.x;
    if (e >= N_EDGES) return;
    int r = rowIdx[e], c = colIdx[e];
    float dx = pos[c * 3 + 0] - pos[r * 3 + 0];
    float dy = pos[c * 3 + 1] - pos[r * 3 + 1];
    float dz = pos[c * 3 + 2] - pos[r * 3 + 2];
    float d = sqrtf(dx * dx + dy * dy + dz * dz);
    *(float4*)&g_ea[e * 4] = make_float4(dx, dy, dz, d);
}

// convert agg -> bf16 mirror, then re-zero agg for the next layer
__global__ void cvt_agg_kernel() {
    int gid = blockIdx.x * blockDim.x + threadIdx.x;
    float4* src = (float4*)g_agg;
    float4 a = src[2 * gid];
    float4 b = src[2 * gid + 1];
    uint4 o;
    o.x = pack_bf2(a.x, a.y);
    o.y = pack_bf2(a.z, a.w);
    o.z = pack_bf2(b.x, b.y);
    o.w = pack_bf2(b.z, b.w);
    ((uint4*)g_aggb)[gid] = o;
    float4 z = make_float4(0.f, 0.f, 0.f, 0.f);
    src[2 * gid] = z;
    src[2 * gid + 1] = z;
}

// ---------------------------------------------------------------- fused edge MLP
__global__ __launch_bounds__(256, 2)
void edge_kernel(int layer,
                 const float* __restrict__ be1, const float* __restrict__ be2,
                 const float* __restrict__ be3,
                 const int* __restrict__ rowIdx, const int* __restrict__ colIdx) {
    extern __shared__ __align__(16) unsigned smem_u[];
    int* s_col = (int*)smem_u;
    int* s_row = s_col + 128;
    unsigned* sActs = smem_u + ACTS_OFF / 4;
    unsigned* sA8 = smem_u + ACTS_OFF / 4;    // ea-tail tile aliases acts start

    unsigned sbase;
    asm("{ .reg .u64 t; cvta.to.shared.u64 t, %1; cvt.u32.u64 %0, t; }"
        : "=r"(sbase) : "l"(smem_u));
    const unsigned actsB = sbase + ACTS_OFF;
    const unsigned a8B = actsB;
    const unsigned abufB[2] = {sbase + ABUF0_OFF, sbase + ABUF1_OFF};
    const unsigned bbufB[2] = {sbase + BBUF0_OFF, sbase + BBUF1_OFF};

    const __nv_bfloat16* W1 = &g_We1b[(size_t)layer * KE_PAD * H];
    const __nv_bfloat16* W2 = &g_We2b[(size_t)layer * H * H];
    const __nv_bfloat16* W3 = &g_We3b[(size_t)layer * H * H];

    int tid = threadIdx.x;
    int eb = blockIdx.x * BM;

    if (tid < 128) s_col[tid] = colIdx[eb + tid];
    else           s_row[tid - 128] = rowIdx[eb + tid - 128];
    __syncthreads();

    int warp = tid >> 5, lane = tid & 31;
    int lr = lane >> 2, lc = lane & 3;
    int wm = (warp & 1) * 64;
    int wn = (warp >> 1) * 32;

    int rA = tid >> 1, halfA = tid & 1;
    int rB = tid >> 3;
    int cB = (tid & 7) * 16;

    // ea-tail tile (ea + rel_mom), pitch 48B, at acts start (read only during GEMM1)
    if (tid < 128) {
        int r = tid;
        float4 ea = *(const float4*)&g_ea[(eb + r) * 4];
        int ci = s_col[r] * H, ri = s_row[r] * H;
        float rm0 = g_h[ci + 3] - g_h[ri + 3];
        float rm1 = g_h[ci + 4] - g_h[ri + 4];
        float rm2 = g_h[ci + 5] - g_h[ri + 5];
        unsigned* dst = &sA8[r * 12];
        dst[0] = pack_bf2(ea.x, ea.y);
        dst[1] = pack_bf2(ea.z, ea.w);
        dst[2] = pack_bf2(rm0, rm1);
        dst[3] = pack_bf2(rm2, 0.f);
        dst[4] = 0u; dst[5] = 0u; dst[6] = 0u; dst[7] = 0u;
    }

    float d[4][4][4];
#pragma unroll
    for (int mt = 0; mt < 4; mt++)
#pragma unroll
        for (int nt = 0; nt < 4; nt++)
#pragma unroll
            for (int i = 0; i < 4; i++) d[mt][nt][i] = 0.f;

    auto issueA = [&](int ch, int p) {
        int node = (ch < 4) ? s_col[rA] : s_row[rA];
        int kbase = (ch & 3) * 32;
        cp16x2(abufB[p] + rA * 80 + halfA * 32,
               &g_hb[(size_t)node * H + kbase + halfA * 16]);
    };
    auto issueB = [&](const __nv_bfloat16* Wb, int ch, int p) {
        cp16x2(bbufB[p] + rB * 272 + cB * 2,
               &Wb[(size_t)(ch * 32 + rB) * H + cB]);
    };

    // ===== GEMM1: K = 288 padded (9 chunks, double-buffered)
    issueA(0, 0);
    issueB(W1, 0, 0);
    CP_COMMIT;

    for (int ch = 0; ch <= 8; ch++) {
        int p = ch & 1;
        if (ch < 8) {
            int p1 = (ch + 1) & 1;
            if (ch + 1 < 8) issueA(ch + 1, p1);
            issueB(W1, ch + 1, p1);
            CP_COMMIT;
            CP_WAIT1;
        } else {
            CP_WAIT0;
        }
        __syncthreads();
        int nk16 = (ch < 8) ? 2 : 1;
        for (int k16 = 0; k16 < nk16; k16++) {
            int k0 = k16 * 16;
            unsigned a[4][4], b[4][2];
            if (ch < 8) {
#pragma unroll
                for (int mt = 0; mt < 4; mt++)
                    ldsm_x4(a[mt][0], a[mt][1], a[mt][2], a[mt][3],
                            abufB[p] + (wm + mt * 16 + (lane & 15)) * 80
                                     + (k0 + ((lane >> 4) << 3)) * 2);
            } else {
#pragma unroll
                for (int mt = 0; mt < 4; mt++)
                    ldsm_x4(a[mt][0], a[mt][1], a[mt][2], a[mt][3],
                            a8B + (wm + mt * 16 + (lane & 15)) * 48
                                + ((lane >> 4) << 3) * 2);
            }
#pragma unroll
            for (int np = 0; np < 2; np++)
                ldsm_x4t(b[2 * np][0], b[2 * np][1], b[2 * np + 1][0], b[2 * np + 1][1],
                         bbufB[p] + (k0 + (lane & 7) + (lane & 8)) * 272
                                  + (wn + np * 16 + ((lane >> 4) << 3)) * 2);
#pragma unroll
            for (int mt = 0; mt < 4; mt++)
#pragma unroll
                for (int nt = 0; nt < 4; nt++) mma_bf16(d[mt][nt], a[mt], b[nt]);
        }
        __syncthreads();
    }

    issueB(W2, 0, 0);
    CP_COMMIT;

    // epilogue1: bias + relu -> acts
#pragma unroll
    for (int mt = 0; mt < 4; mt++)
#pragma unroll
        for (int nt = 0; nt < 4; nt++) {
            int row = wm + mt * 16 + lr;
            int col = wn + nt * 8 + 2 * lc;
            float2 bv = *(const float2*)&be1[col];
            sActs[(row * 136 + col) >> 1] =
                pack_bf2(fmaxf(d[mt][nt][0] + bv.x, 0.f), fmaxf(d[mt][nt][1] + bv.y, 0.f));
            sActs[((row + 8) * 136 + col) >> 1] =
                pack_bf2(fmaxf(d[mt][nt][2] + bv.x, 0.f), fmaxf(d[mt][nt][3] + bv.y, 0.f));
        }

    // ===== GEMM2
#pragma unroll
    for (int mt = 0; mt < 4; mt++)
#pragma unroll
        for (int nt = 0; nt < 4; nt++)
#pragma unroll
            for (int i = 0; i < 4; i++) d[mt][nt][i] = 0.f;

    for (int ch = 0; ch < 4; ch++) {
        int p = ch & 1;
        if (ch < 3) {
            issueB(W2, ch + 1, (ch + 1) & 1);
            CP_COMMIT;
            CP_WAIT1;
        } else {
            CP_WAIT0;
        }
        __syncthreads();
#pragma unroll
        for (int k16 = 0; k16 < 2; k16++) {
            int kg = ch * 32 + k16 * 16;
            int k0 = k16 * 16;
            unsigned a[4][4], b[4][2];
#pragma unroll
            for (int mt = 0; mt < 4; mt++)
                ldsm_x4(a[mt][0], a[mt][1], a[mt][2], a[mt][3],
                        actsB + (wm + mt * 16 + (lane & 15)) * 272
                              + (kg + ((lane >> 4) << 3)) * 2);
#pragma unroll
            for (int np = 0; np < 2; np++)
                ldsm_x4t(b[2 * np][0], b[2 * np][1], b[2 * np + 1][0], b[2 * np + 1][1],
                         bbufB[p] + (k0 + (lane & 7) + (lane & 8)) * 272
                                  + (wn + np * 16 + ((lane >> 4) << 3)) * 2);
#pragma unroll
            for (int mt = 0; mt < 4; mt++)
#pragma unroll
                for (int nt = 0; nt < 4; nt++) mma_bf16(d[mt][nt], a[mt], b[nt]);
        }
        __syncthreads();
    }

    issueB(W3, 0, 0);
    CP_COMMIT;

#pragma unroll
    for (int mt = 0; mt < 4; mt++)
#pragma unroll
        for (int nt = 0; nt < 4; nt++) {
            int row = wm + mt * 16 + lr;
            int col = wn + nt * 8 + 2 * lc;
            float2 bv = *(const float2*)&be2[col];
            sActs[(row * 136 + col) >> 1] =
                pack_bf2(fmaxf(d[mt][nt][0] + bv.x, 0.f), fmaxf(d[mt][nt][1] + bv.y, 0.f));
            sActs[((row + 8) * 136 + col) >> 1] =
                pack_bf2(fmaxf(d[mt][nt][2] + bv.x, 0.f), fmaxf(d[mt][nt][3] + bv.y, 0.f));
        }

    // ===== GEMM3
#pragma unroll
    for (int mt = 0; mt < 4; mt++)
#pragma unroll
        for (int nt = 0; nt < 4; nt++)
#pragma unroll
            for (int i = 0; i < 4; i++) d[mt][nt][i] = 0.f;

    for (int ch = 0; ch < 4; ch++) {
        int p = ch & 1;
        if (ch < 3) {
            issueB(W3, ch + 1, (ch + 1) & 1);
            CP_COMMIT;
            CP_WAIT1;
        } else {
            CP_WAIT0;
        }
        __syncthreads();
#pragma unroll
        for (int k16 = 0; k16 < 2; k16++) {
            int kg = ch * 32 + k16 * 16;
            int k0 = k16 * 16;
            unsigned a[4][4], b[4][2];
#pragma unroll
            for (int mt = 0; mt < 4; mt++)
                ldsm_x4(a[mt][0], a[mt][1], a[mt][2], a[mt][3],
                        actsB + (wm + mt * 16 + (lane & 15)) * 272
                              + (kg + ((lane >> 4) << 3)) * 2);
#pragma unroll
            for (int np = 0; np < 2; np++)
                ldsm_x4t(b[2 * np][0], b[2 * np][1], b[2 * np + 1][0], b[2 * np + 1][1],
                         bbufB[p] + (k0 + (lane & 7) + (lane & 8)) * 272
                                  + (wn + np * 16 + ((lane >> 4) << 3)) * 2);
#pragma unroll
            for (int mt = 0; mt < 4; mt++)
#pragma unroll
                for (int nt = 0; nt < 4; nt++) mma_bf16(d[mt][nt], a[mt], b[nt]);
        }
        __syncthreads();
    }

    // epilogue3: pair-shuffle v4 reds
#pragma unroll
    for (int mt = 0; mt < 4; mt++)
#pragma unroll
        for (int nt = 0; nt < 4; nt++) {
            int colseg = wn + nt * 8 + ((lc & 2) << 1);
            float4 bv = *(const float4*)&be3[colseg];
            bool ev = (lc & 1) == 0;
            float s0 = ev ? d[mt][nt][2] : d[mt][nt][0];
            float s1 = ev ? d[mt][nt][3] : d[mt][nt][1];
            float r0 = __uint_as_float(__shfl_xor_sync(0xffffffffu, __float_as_uint(s0), 1));
            float r1 = __uint_as_float(__shfl_xor_sync(0xffffffffu, __float_as_uint(s1), 1));
            int e0 = wm + mt * 16 + lr;
            if (ev) {
                int tgt = s_col[e0];
                red_add_f4(&g_agg[(size_t)tgt * H + colseg],
                           d[mt][nt][0] + bv.x, d[mt][nt][1] + bv.y,
                           r0 + bv.z, r1 + bv.w);
            } else {
                int tgt = s_col[e0 + 8];
                red_add_f4(&g_agg[(size_t)tgt * H + colseg],
                           r0 + bv.x, r1 + bv.y,
                           d[mt][nt][2] + bv.z, d[mt][nt][3] + bv.w);
            }
        }
}

// ---------------------------------------------------------------- node MLP
__global__ __launch_bounds__(256, 2)
void node_kernel(int layer,
                 const float* __restrict__ bn1, const float* __restrict__ bn2,
                 const float* __restrict__ bn3,
                 const float* __restrict__ lng, const float* __restrict__ lnb,
                 float* __restrict__ out) {
    extern __shared__ __align__(16) unsigned smem_u[];
    unsigned* sActs = smem_u + NACTS_OFF / 4;
    float* sLN = (float*)(smem_u + NLN_OFF / 4);

    unsigned sbase;
    asm("{ .reg .u64 t; cvta.to.shared.u64 t, %1; cvt.u32.u64 %0, t; }"
        : "=r"(sbase) : "l"(smem_u));
    const unsigned actsB = sbase + NACTS_OFF;
    const unsigned abufB[2] = {sbase + NABUF0_OFF, sbase + NABUF1_OFF};
    const unsigned bbufB[2] = {sbase + NBBUF0_OFF, sbase + NBBUF1_OFF};

    const __nv_bfloat16* W1 = &g_Wn1b[(size_t)layer * KN * H];
    const __nv_bfloat16* W2 = &g_Wn2b[(size_t)layer * H * H];
    const __nv_bfloat16* W3 = &g_Wn3b[(size_t)layer * H * H];

    int tid = threadIdx.x;
    int nb = blockIdx.x * BM;

    int warp = tid >> 5, lane = tid & 31;
    int lr = lane >> 2, lc = lane & 3;
    int wm = (warp & 1) * 64;
    int wn = (warp >> 1) * 32;

    int rA = tid >> 1, halfA = tid & 1;
    int rB = tid >> 3;
    int cB = (tid & 7) * 16;
    int nodeA = nb + rA; if (nodeA >= N_NODES) nodeA = N_NODES - 1;

    float d[4][4][4];
#pragma unroll
    for (int mt = 0; mt < 4; mt++)
#pragma unroll
        for (int nt = 0; nt < 4; nt++)
#pragma unroll
            for (int i = 0; i < 4; i++) d[mt][nt][i] = 0.f;

    auto issueA = [&](int ch, int p) {
        const __nv_bfloat16* src = (ch < 4)
            ? &g_hb[(size_t)nodeA * H + ch * 32 + halfA * 16]
            : &g_aggb[(size_t)nodeA * H + (ch - 4) * 32 + halfA * 16];
        cp16x2(abufB[p] + rA * 80 + halfA * 32, src);
    };
    auto issueB = [&](const __nv_bfloat16* Wb, int ch, int p) {
        cp16x2(bbufB[p] + rB * 272 + cB * 2,
               &Wb[(size_t)(ch * 32 + rB) * H + cB]);
    };

    issueA(0, 0);
    issueB(W1, 0, 0);
    CP_COMMIT;

    for (int ch = 0; ch < 8; ch++) {
        int p = ch & 1;
        if (ch < 7) {
            int p1 = (ch + 1) & 1;
            issueA(ch + 1, p1);
            issueB(W1, ch + 1, p1);
            CP_COMMIT;
            CP_WAIT1;
        } else {
            CP_WAIT0;
        }
        __syncthreads();
#pragma unroll
        for (int k16 = 0; k16 < 2; k16++) {
            int k0 = k16 * 16;
            unsigned a[4][4], b[4][2];
#pragma unroll
            for (int mt = 0; mt < 4; mt++)
                ldsm_x4(a[mt][0], a[mt][1], a[mt][2], a[mt][3],
                        abufB[p] + (wm + mt * 16 + (lane & 15)) * 80
                                 + (k0 + ((lane >> 4) << 3)) * 2);
#pragma unroll
            for (int np = 0; np < 2; np++)
                ldsm_x4t(b[2 * np][0], b[2 * np][1], b[2 * np + 1][0], b[2 * np + 1][1],
                         bbufB[p] + (k0 + (lane & 7) + (lane & 8)) * 272
                                  + (wn + np * 16 + ((lane >> 4) << 3)) * 2);
#pragma unroll
            for (int mt = 0; mt < 4; mt++)
#pragma unroll
                for (int nt = 0; nt < 4; nt++) mma_bf16(d[mt][nt], a[mt], b[nt]);
        }
        __syncthreads();
    }

    issueB(W2, 0, 0);
    CP_COMMIT;

#pragma unroll
    for (int mt = 0; mt < 4; mt++)
#pragma unroll
        for (int nt = 0; nt < 4; nt++) {
            int row = wm + mt * 16 + lr;
            int col = wn + nt * 8 + 2 * lc;
            float2 bv = *(const float2*)&bn1[col];
            sActs[(row * 136 + col) >> 1] =
                pack_bf2(fmaxf(d[mt][nt][0] + bv.x, 0.f), fmaxf(d[mt][nt][1] + bv.y, 0.f));
            sActs[((row + 8) * 136 + col) >> 1] =
                pack_bf2(fmaxf(d[mt][nt][2] + bv.x, 0.f), fmaxf(d[mt][nt][3] + bv.y, 0.f));
        }

#pragma unroll
    for (int mt = 0; mt < 4; mt++)
#pragma unroll
        for (int nt = 0; nt < 4; nt++)
#pragma unroll
            for (int i = 0; i < 4; i++) d[mt][nt][i] = 0.f;

    for (int ch = 0; ch < 4; ch++) {
        int p = ch & 1;
        if (ch < 3) {
            issueB(W2, ch + 1, (ch + 1) & 1);
            CP_COMMIT;
            CP_WAIT1;
        } else {
            CP_WAIT0;
        }
        __syncthreads();
#pragma unroll
        for (int k16 = 0; k16 < 2; k16++) {
            int kg = ch * 32 + k16 * 16;
            int k0 = k16 * 16;
            unsigned a[4][4], b[4][2];
#pragma unroll
            for (int mt = 0; mt < 4; mt++)
                ldsm_x4(a[mt][0], a[mt][1], a[mt][2], a[mt][3],
                        actsB + (wm + mt * 16 + (lane & 15)) * 272
                              + (kg + ((lane >> 4) << 3)) * 2);
#pragma unroll
            for (int np = 0; np < 2; np++)
                ldsm_x4t(b[2 * np][0], b[2 * np][1], b[2 * np + 1][0], b[2 * np + 1][1],
                         bbufB[p] + (k0 + (lane & 7) + (lane & 8)) * 272
                                  + (wn + np * 16 + ((lane >> 4) << 3)) * 2);
#pragma unroll
            for (int mt = 0; mt < 4; mt++)
#pragma unroll
                for (int nt = 0; nt < 4; nt++) mma_bf16(d[mt][nt], a[mt], b[nt]);
        }
        __syncthreads();
    }

    issueB(W3, 0, 0);
    CP_COMMIT;

#pragma unroll
    for (int mt = 0; mt < 4; mt++)
#pragma unroll
        for (int nt = 0; nt < 4; nt++) {
            int row = wm + mt * 16 + lr;
            int col = wn + nt * 8 + 2 * lc;
            float2 bv = *(const float2*)&bn2[col];
            sActs[(row * 136 + col) >> 1] =
                pack_bf2(fmaxf(d[mt][nt][0] + bv.x, 0.f), fmaxf(d[mt][nt][1] + bv.y, 0.f));
            sActs[((row + 8) * 136 + col) >> 1] =
                pack_bf2(fmaxf(d[mt][nt][2] + bv.x, 0.f), fmaxf(d[mt][nt][3] + bv.y, 0.f));
        }

#pragma unroll
    for (int mt = 0; mt < 4; mt++)
#pragma unroll
        for (int nt = 0; nt < 4; nt++)
#pragma unroll
            for (int i = 0; i < 4; i++) d[mt][nt][i] = 0.f;

    for (int ch = 0; ch < 4; ch++) {
        int p = ch & 1;
        if (ch < 3) {
            issueB(W3, ch + 1, (ch + 1) & 1);
            CP_COMMIT;
            CP_WAIT1;
        } else {
            CP_WAIT0;
        }
        __syncthreads();
#pragma unroll
        for (int k16 = 0; k16 < 2; k16++) {
            int kg = ch * 32 + k16 * 16;
            int k0 = k16 * 16;
            unsigned a[4][4], b[4][2];
#pragma unroll
            for (int mt = 0; mt < 4; mt++)
                ldsm_x4(a[mt][0], a[mt][1], a[mt][2], a[mt][3],
                        actsB + (wm + mt * 16 + (lane & 15)) * 272
                              + (kg + ((lane >> 4) << 3)) * 2);
#pragma unroll
            for (int np = 0; np < 2; np++)
                ldsm_x4t(b[2 * np][0], b[2 * np][1], b[2 * np + 1][0], b[2 * np + 1][1],
                         bbufB[p] + (k0 + (lane & 7) + (lane & 8)) * 272
                                  + (wn + np * 16 + ((lane >> 4) << 3)) * 2);
#pragma unroll
            for (int mt = 0; mt < 4; mt++)
#pragma unroll
                for (int nt = 0; nt < 4; nt++) mma_bf16(d[mt][nt], a[mt], b[nt]);
        }
        __syncthreads();
    }

#pragma unroll
    for (int mt = 0; mt < 4; mt++)
#pragma unroll
        for (int nt = 0; nt < 4; nt++) {
            int row = wm + mt * 16 + lr;
            int col = wn + nt * 8 + 2 * lc;
            float2 bv = *(const float2*)&bn3[col];
            int n0 = nb + row, n1 = nb + row + 8;
            float2 h0 = make_float2(0.f, 0.f), h1 = make_float2(0.f, 0.f);
            if (n0 < N_NODES) h0 = *(const float2*)&g_h[n0 * H + col];
            if (n1 < N_NODES) h1 = *(const float2*)&g_h[n1 * H + col];
            *(float2*)&sLN[row * 132 + col] =
                make_float2(h0.x + d[mt][nt][0] + bv.x, h0.y + d[mt][nt][1] + bv.y);
            *(float2*)&sLN[(row + 8) * 132 + col] =
                make_float2(h1.x + d[mt][nt][2] + bv.x, h1.y + d[mt][nt][3] + bv.y);
        }
    __syncthreads();

    {
        for (int r = warp * 16; r < warp * 16 + 16; r++) {
            int node = nb + r;
            float v0 = sLN[r * 132 + lane];
            float v1 = sLN[r * 132 + lane + 32];
            float v2 = sLN[r * 132 + lane + 64];
            float v3 = sLN[r * 132 + lane + 96];
            float s = v0 + v1 + v2 + v3;
            float q = v0 * v0 + v1 * v1 + v2 * v2 + v3 * v3;
#pragma unroll
            for (int off = 16; off > 0; off >>= 1) {
                s += __shfl_xor_sync(0xffffffffu, s, off);
                q += __shfl_xor_sync(0xffffffffu, q, off);
            }
            float mean = s * (1.f / 128.f);
            float var = q * (1.f / 128.f) - mean * mean;
            float rstd = rsqrtf(var + 1e-5f);
            if (node < N_NODES) {
                float o0 = (v0 - mean) * rstd * lng[lane]      + lnb[lane];
                float o1 = (v1 - mean) * rstd * lng[lane + 32] + lnb[lane + 32];
                float o2 = (v2 - mean) * rstd * lng[lane + 64] + lnb[lane + 64];
                float o3 = (v3 - mean) * rstd * lng[lane + 96] + lnb[lane + 96];
                out[node * H + lane]      = o0;
                out[node * H + lane + 32] = o1;
                out[node * H + lane + 64] = o2;
                out[node * H + lane + 96] = o3;
                g_hb[node * H + lane]      = __float2bfloat16(o0);
                g_hb[node * H + lane + 32] = __float2bfloat16(o1);
                g_hb[node * H + lane + 64] = __float2bfloat16(o2);
                g_hb[node * H + lane + 96] = __float2bfloat16(o3);
            }
        }
    }
}

// ----------------------------------------------------------------
extern "C" void kernel_launch(void* const* d_in, const int* in_sizes, int n_in,
                              void* d_out, int out_size) {
    const float* x    = (const float*)d_in[0];
    const float* pos  = (const float*)d_in[1];
    const int*   ei   = (const int*)d_in[2];
    const float* W_in = (const float*)d_in[3];
    const float* b_in = (const float*)d_in[4];
    const float* We1  = (const float*)d_in[5];
    const float* be1  = (const float*)d_in[6];
    const float* We2  = (const float*)d_in[7];
    const float* be2  = (const float*)d_in[8];
    const float* We3  = (const float*)d_in[9];
    const float* be3  = (const float*)d_in[10];
    const float* Wn1  = (const float*)d_in[11];
    const float* bn1  = (const float*)d_in[12];
    const float* Wn2  = (const float*)d_in[13];
    const float* bn2  = (const float*)d_in[14];
    const float* Wn3  = (const float*)d_in[15];
    const float* bn3  = (const float*)d_in[16];
    const float* ln_g = (const float*)d_in[17];
    const float* ln_b = (const float*)d_in[18];

    const int* rowIdx = ei;
    const int* colIdx = ei + N_EDGES;

    cudaFuncSetAttribute(edge_kernel, cudaFuncAttributeMaxDynamicSharedMemorySize, SMEM_EDGE);
    cudaFuncSetAttribute(node_kernel, cudaFuncAttributeMaxDynamicSharedMemorySize, SMEM_NODE);
    // full shared-memory carveout so 3 CTAs/SM can be resident (regs stay at 128: no spills)
    cudaFuncSetAttribute(edge_kernel, cudaFuncAttributePreferredSharedMemoryCarveout, 100);
    cudaFuncSetAttribute(node_kernel, cudaFuncAttributePreferredSharedMemoryCarveout, 100);

    float* hptr = nullptr;
    cudaGetSymbolAddress((void**)&hptr, g_h);

    int prep_total = LAYERS * KE_PAD * H + 2 * LAYERS * H * H
                   + LAYERS * KN * H + 2 * LAYERS * H * H;
    // launch order keeps edge_kernel at process-launch #4 (ncu capture slot)
    prep_weights<<<(prep_total + 255) / 256, 256>>>(We1, We2, We3, Wn1, Wn2, Wn3);
    embed_kernel<<<(N_NODES * H + 255) / 256, 256>>>(x, W_in, b_in);  // also zeroes g_agg
    ea_kernel<<<(N_EDGES + 255) / 256, 256>>>(pos, rowIdx, colIdx);

    int edge_blocks = N_EDGES / BM;
    int node_blocks = (N_NODES + BM - 1) / BM;
    int cvt_blocks = (N_NODES * H / 8) / 256;

    for (int l = 0; l < LAYERS; l++) {
        edge_kernel<<<edge_blocks, 256, SMEM_EDGE>>>(
            l, be1 + l * H, be2 + l * H, be3 + l * H, rowIdx, colIdx);
        cvt_agg_kernel<<<cvt_blocks, 256>>>();
        float* outp = (l == LAYERS - 1) ? (float*)d_out : hptr;
        node_kernel<<<node_blocks, 256, SMEM_NODE>>>(
            l, bn1 + l * H, bn2 + l * H, bn3 + l * H,
            ln_g + l * H, ln_b + l * H, outp);
    }
}

// round 15
// speedup vs baseline: 1.4628x; 1.0601x over previous
#include <cuda_runtime.h>
#include <cuda_bf16.h>
#include <cstdint>
#include <math.h>

#define N_NODES 50000
#define N_EDGES 800000
#define H 128
#define LAYERS 4
#define KE 263
#define KN 256
#define BM 128
#define KE_PAD 288

// edge + node shared smem layout (bytes), total 73728
#define ACTS_OFF  1024
#define ABUF0_OFF 35840
#define ABUF1_OFF 46080
#define BBUF0_OFF 56320
#define BBUF1_OFF 65024
#define SMEM_EDGE 73728

#define NACTS_OFF  1024
#define NABUF0_OFF 35840
#define NABUF1_OFF 46080
#define NBBUF0_OFF 56320
#define NBBUF1_OFF 65024
#define SMEM_NODE  73728
#define NLN_OFF    1024

__device__ float g_h[N_NODES * H];
__device__ float g_agg[N_NODES * H];
__device__ float g_ea[N_EDGES * 4];
__device__ __nv_bfloat16 g_hb[N_NODES * H];
__device__ __nv_bfloat16 g_We1b[LAYERS * KE_PAD * H];
__device__ __nv_bfloat16 g_We2b[LAYERS * H * H];
__device__ __nv_bfloat16 g_We3b[LAYERS * H * H];
__device__ __nv_bfloat16 g_Wn1b[LAYERS * KN * H];
__device__ __nv_bfloat16 g_Wn2b[LAYERS * H * H];
__device__ __nv_bfloat16 g_Wn3b[LAYERS * H * H];

#define CP_COMMIT asm volatile("cp.async.commit_group;" ::: "memory")
#define CP_WAIT1  asm volatile("cp.async.wait_group 1;" ::: "memory")
#define CP_WAIT0  asm volatile("cp.async.wait_group 0;" ::: "memory")

__device__ __forceinline__ void cp16x2(unsigned dst, const void* src) {
    asm volatile("cp.async.cg.shared.global [%0], [%1], 16;\n\t"
                 "cp.async.cg.shared.global [%2], [%3], 16;"
                 :: "r"(dst), "l"(src), "r"(dst + 16), "l"((const char*)src + 16) : "memory");
}
__device__ __forceinline__ void red_add_f4(float* p, float a, float b, float c, float d) {
    asm volatile("red.global.add.v4.f32 [%0], {%1,%2,%3,%4};"
                 :: "l"(p), "f"(a), "f"(b), "f"(c), "f"(d) : "memory");
}
__device__ __forceinline__ unsigned pack_bf2(float lo, float hi) {
    __nv_bfloat162 v = __floats2bfloat162_rn(lo, hi);
    return *(unsigned*)&v;
}
__device__ __forceinline__ void ldsm_x4(unsigned& r0, unsigned& r1, unsigned& r2, unsigned& r3,
                                        unsigned addr) {
    asm volatile("ldmatrix.sync.aligned.m8n8.x4.shared.b16 {%0,%1,%2,%3}, [%4];"
                 : "=r"(r0), "=r"(r1), "=r"(r2), "=r"(r3) : "r"(addr));
}
__device__ __forceinline__ void ldsm_x4t(unsigned& r0, unsigned& r1, unsigned& r2, unsigned& r3,
                                         unsigned addr) {
    asm volatile("ldmatrix.sync.aligned.m8n8.x4.trans.shared.b16 {%0,%1,%2,%3}, [%4];"
                 : "=r"(r0), "=r"(r1), "=r"(r2), "=r"(r3) : "r"(addr));
}
__device__ __forceinline__ void mma_bf16(float d[4], const unsigned a[4], const unsigned b[2]) {
    asm volatile("mma.sync.aligned.m16n8k16.row.col.f32.bf16.bf16.f32 "
                 "{%0,%1,%2,%3}, {%4,%5,%6,%7}, {%8,%9}, {%0,%1,%2,%3};"
                 : "+f"(d[0]), "+f"(d[1]), "+f"(d[2]), "+f"(d[3])
                 : "r"(a[0]), "r"(a[1]), "r"(a[2]), "r"(a[3]), "r"(b[0]), "r"(b[1]));
}

// ---------------------------------------------------------------- weight prep (fp32 -> bf16)
__global__ void prep_weights(const float* __restrict__ We1,
                             const float* __restrict__ We2,
                             const float* __restrict__ We3,
                             const float* __restrict__ Wn1,
                             const float* __restrict__ Wn2,
                             const float* __restrict__ Wn3) {
    int id = blockIdx.x * blockDim.x + threadIdx.x;
    const int n1 = LAYERS * KE_PAD * H;
    const int n2 = LAYERS * H * H;
    const int n3 = LAYERS * KN * H;
    if (id < n1) {
        int l = id / (KE_PAD * H);
        int rem = id % (KE_PAD * H);
        int r = rem / H, c = rem % H;
        float v = (r < KE) ? We1[((size_t)l * KE + r) * H + c] : 0.f;
        g_We1b[id] = __float2bfloat16(v);
    } else if (id < n1 + n2) {
        g_We2b[id - n1] = __float2bfloat16(We2[id - n1]);
    } else if (id < n1 + 2 * n2) {
        g_We3b[id - n1 - n2] = __float2bfloat16(We3[id - n1 - n2]);
    } else if (id < n1 + 2 * n2 + n3) {
        int k = id - n1 - 2 * n2;
        g_Wn1b[k] = __float2bfloat16(Wn1[k]);
    } else if (id < n1 + 2 * n2 + n3 + n2) {
        int k = id - n1 - 2 * n2 - n3;
        g_Wn2b[k] = __float2bfloat16(Wn2[k]);
    } else if (id < n1 + 2 * n2 + n3 + 2 * n2) {
        int k = id - n1 - 2 * n2 - n3 - n2;
        g_Wn3b[k] = __float2bfloat16(Wn3[k]);
    }
}

// ---------------------------------------------------------------- embed (+ zero g_agg)
__global__ void embed_kernel(const float* __restrict__ x,
                             const float* __restrict__ W,
                             const float* __restrict__ b) {
    int gid = blockIdx.x * blockDim.x + threadIdx.x;
    if (gid >= N_NODES * H) return;
    int i = gid >> 7;
    int j = gid & (H - 1);
    const float* xr = x + i * 16;
    float acc = b[j];
#pragma unroll
    for (int k = 0; k < 16; k++) acc += xr[k] * W[k * H + j];
    g_h[gid] = acc;
    g_hb[gid] = __float2bfloat16(acc);
    g_agg[gid] = 0.f;
}

__global__ void ea_kernel(const float* __restrict__ pos,
                          const int* __restrict__ rowIdx,
                          const int* __restrict__ colIdx) {
    int e = blockIdx.x * blockDim.x + threadIdx.x;
    if (e >= N_EDGES) return;
    int r = rowIdx[e], c = colIdx[e];
    float dx = pos[c * 3 + 0] - pos[r * 3 + 0];
    float dy = pos[c * 3 + 1] - pos[r * 3 + 1];
    float dz = pos[c * 3 + 2] - pos[r * 3 + 2];
    float d = sqrtf(dx * dx + dy * dy + dz * dz);
    *(float4*)&g_ea[e * 4] = make_float4(dx, dy, dz, d);
}

// ---------------------------------------------------------------- fused edge MLP (exact R12)
__global__ __launch_bounds__(256, 2)
void edge_kernel(int layer,
                 const float* __restrict__ be1, const float* __restrict__ be2,
                 const float* __restrict__ be3,
                 const int* __restrict__ rowIdx, const int* __restrict__ colIdx) {
    extern __shared__ __align__(16) unsigned smem_u[];
    int* s_col = (int*)smem_u;
    int* s_row = s_col + 128;
    unsigned* sActs = smem_u + ACTS_OFF / 4;
    unsigned* sA8 = smem_u + ACTS_OFF / 4;    // ea-tail tile aliases acts start

    unsigned sbase;
    asm("{ .reg .u64 t; cvta.to.shared.u64 t, %1; cvt.u32.u64 %0, t; }"
        : "=r"(sbase) : "l"(smem_u));
    const unsigned actsB = sbase + ACTS_OFF;
    const unsigned a8B = actsB;
    const unsigned abufB[2] = {sbase + ABUF0_OFF, sbase + ABUF1_OFF};
    const unsigned bbufB[2] = {sbase + BBUF0_OFF, sbase + BBUF1_OFF};

    const __nv_bfloat16* W1 = &g_We1b[(size_t)layer * KE_PAD * H];
    const __nv_bfloat16* W2 = &g_We2b[(size_t)layer * H * H];
    const __nv_bfloat16* W3 = &g_We3b[(size_t)layer * H * H];

    int tid = threadIdx.x;
    int eb = blockIdx.x * BM;

    if (tid < 128) s_col[tid] = colIdx[eb + tid];
    else           s_row[tid - 128] = rowIdx[eb + tid - 128];
    __syncthreads();

    int warp = tid >> 5, lane = tid & 31;
    int lr = lane >> 2, lc = lane & 3;
    int wm = (warp & 1) * 64;
    int wn = (warp >> 1) * 32;

    int rA = tid >> 1, halfA = tid & 1;
    int rB = tid >> 3;
    int cB = (tid & 7) * 16;

    if (tid < 128) {
        int r = tid;
        float4 ea = *(const float4*)&g_ea[(eb + r) * 4];
        int ci = s_col[r] * H, ri = s_row[r] * H;
        float rm0 = g_h[ci + 3] - g_h[ri + 3];
        float rm1 = g_h[ci + 4] - g_h[ri + 4];
        float rm2 = g_h[ci + 5] - g_h[ri + 5];
        unsigned* dst = &sA8[r * 12];
        dst[0] = pack_bf2(ea.x, ea.y);
        dst[1] = pack_bf2(ea.z, ea.w);
        dst[2] = pack_bf2(rm0, rm1);
        dst[3] = pack_bf2(rm2, 0.f);
        dst[4] = 0u; dst[5] = 0u; dst[6] = 0u; dst[7] = 0u;
    }

    float d[4][4][4];
#pragma unroll
    for (int mt = 0; mt < 4; mt++)
#pragma unroll
        for (int nt = 0; nt < 4; nt++)
#pragma unroll
            for (int i = 0; i < 4; i++) d[mt][nt][i] = 0.f;

    auto issueA = [&](int ch, int p) {
        int node = (ch < 4) ? s_col[rA] : s_row[rA];
        int kbase = (ch & 3) * 32;
        cp16x2(abufB[p] + rA * 80 + halfA * 32,
               &g_hb[(size_t)node * H + kbase + halfA * 16]);
    };
    auto issueB = [&](const __nv_bfloat16* Wb, int ch, int p) {
        cp16x2(bbufB[p] + rB * 272 + cB * 2,
               &Wb[(size_t)(ch * 32 + rB) * H + cB]);
    };

    issueA(0, 0);
    issueB(W1, 0, 0);
    CP_COMMIT;

    for (int ch = 0; ch <= 8; ch++) {
        int p = ch & 1;
        if (ch < 8) {
            int p1 = (ch + 1) & 1;
            if (ch + 1 < 8) issueA(ch + 1, p1);
            issueB(W1, ch + 1, p1);
            CP_COMMIT;
            CP_WAIT1;
        } else {
            CP_WAIT0;
        }
        __syncthreads();
        int nk16 = (ch < 8) ? 2 : 1;
        for (int k16 = 0; k16 < nk16; k16++) {
            int k0 = k16 * 16;
            unsigned a[4][4], b[4][2];
            if (ch < 8) {
#pragma unroll
                for (int mt = 0; mt < 4; mt++)
                    ldsm_x4(a[mt][0], a[mt][1], a[mt][2], a[mt][3],
                            abufB[p] + (wm + mt * 16 + (lane & 15)) * 80
                                     + (k0 + ((lane >> 4) << 3)) * 2);
            } else {
#pragma unroll
                for (int mt = 0; mt < 4; mt++)
                    ldsm_x4(a[mt][0], a[mt][1], a[mt][2], a[mt][3],
                            a8B + (wm + mt * 16 + (lane & 15)) * 48
                                + ((lane >> 4) << 3) * 2);
            }
#pragma unroll
            for (int np = 0; np < 2; np++)
                ldsm_x4t(b[2 * np][0], b[2 * np][1], b[2 * np + 1][0], b[2 * np + 1][1],
                         bbufB[p] + (k0 + (lane & 7) + (lane & 8)) * 272
                                  + (wn + np * 16 + ((lane >> 4) << 3)) * 2);
#pragma unroll
            for (int mt = 0; mt < 4; mt++)
#pragma unroll
                for (int nt = 0; nt < 4; nt++) mma_bf16(d[mt][nt], a[mt], b[nt]);
        }
        __syncthreads();
    }

    issueB(W2, 0, 0);
    CP_COMMIT;

#pragma unroll
    for (int mt = 0; mt < 4; mt++)
#pragma unroll
        for (int nt = 0; nt < 4; nt++) {
            int row = wm + mt * 16 + lr;
            int col = wn + nt * 8 + 2 * lc;
            float2 bv = *(const float2*)&be1[col];
            sActs[(row * 136 + col) >> 1] =
                pack_bf2(fmaxf(d[mt][nt][0] + bv.x, 0.f), fmaxf(d[mt][nt][1] + bv.y, 0.f));
            sActs[((row + 8) * 136 + col) >> 1] =
                pack_bf2(fmaxf(d[mt][nt][2] + bv.x, 0.f), fmaxf(d[mt][nt][3] + bv.y, 0.f));
        }

#pragma unroll
    for (int mt = 0; mt < 4; mt++)
#pragma unroll
        for (int nt = 0; nt < 4; nt++)
#pragma unroll
            for (int i = 0; i < 4; i++) d[mt][nt][i] = 0.f;

    for (int ch = 0; ch < 4; ch++) {
        int p = ch & 1;
        if (ch < 3) {
            issueB(W2, ch + 1, (ch + 1) & 1);
            CP_COMMIT;
            CP_WAIT1;
        } else {
            CP_WAIT0;
        }
        __syncthreads();
#pragma unroll
        for (int k16 = 0; k16 < 2; k16++) {
            int kg = ch * 32 + k16 * 16;
            int k0 = k16 * 16;
            unsigned a[4][4], b[4][2];
#pragma unroll
            for (int mt = 0; mt < 4; mt++)
                ldsm_x4(a[mt][0], a[mt][1], a[mt][2], a[mt][3],
                        actsB + (wm + mt * 16 + (lane & 15)) * 272
                              + (kg + ((lane >> 4) << 3)) * 2);
#pragma unroll
            for (int np = 0; np < 2; np++)
                ldsm_x4t(b[2 * np][0], b[2 * np][1], b[2 * np + 1][0], b[2 * np + 1][1],
                         bbufB[p] + (k0 + (lane & 7) + (lane & 8)) * 272
                                  + (wn + np * 16 + ((lane >> 4) << 3)) * 2);
#pragma unroll
            for (int mt = 0; mt < 4; mt++)
#pragma unroll
                for (int nt = 0; nt < 4; nt++) mma_bf16(d[mt][nt], a[mt], b[nt]);
        }
        __syncthreads();
    }

    issueB(W3, 0, 0);
    CP_COMMIT;

#pragma unroll
    for (int mt = 0; mt < 4; mt++)
#pragma unroll
        for (int nt = 0; nt < 4; nt++) {
            int row = wm + mt * 16 + lr;
            int col = wn + nt * 8 + 2 * lc;
            float2 bv = *(const float2*)&be2[col];
            sActs[(row * 136 + col) >> 1] =
                pack_bf2(fmaxf(d[mt][nt][0] + bv.x, 0.f), fmaxf(d[mt][nt][1] + bv.y, 0.f));
            sActs[((row + 8) * 136 + col) >> 1] =
                pack_bf2(fmaxf(d[mt][nt][2] + bv.x, 0.f), fmaxf(d[mt][nt][3] + bv.y, 0.f));
        }

#pragma unroll
    for (int mt = 0; mt < 4; mt++)
#pragma unroll
        for (int nt = 0; nt < 4; nt++)
#pragma unroll
            for (int i = 0; i < 4; i++) d[mt][nt][i] = 0.f;

    for (int ch = 0; ch < 4; ch++) {
        int p = ch & 1;
        if (ch < 3) {
            issueB(W3, ch + 1, (ch + 1) & 1);
            CP_COMMIT;
            CP_WAIT1;
        } else {
            CP_WAIT0;
        }
        __syncthreads();
#pragma unroll
        for (int k16 = 0; k16 < 2; k16++) {
            int kg = ch * 32 + k16 * 16;
            int k0 = k16 * 16;
            unsigned a[4][4], b[4][2];
#pragma unroll
            for (int mt = 0; mt < 4; mt++)
                ldsm_x4(a[mt][0], a[mt][1], a[mt][2], a[mt][3],
                        actsB + (wm + mt * 16 + (lane & 15)) * 272
                              + (kg + ((lane >> 4) << 3)) * 2);
#pragma unroll
            for (int np = 0; np < 2; np++)
                ldsm_x4t(b[2 * np][0], b[2 * np][1], b[2 * np + 1][0], b[2 * np + 1][1],
                         bbufB[p] + (k0 + (lane & 7) + (lane & 8)) * 272
                                  + (wn + np * 16 + ((lane >> 4) << 3)) * 2);
#pragma unroll
            for (int mt = 0; mt < 4; mt++)
#pragma unroll
                for (int nt = 0; nt < 4; nt++) mma_bf16(d[mt][nt], a[mt], b[nt]);
        }
        __syncthreads();
    }

#pragma unroll
    for (int mt = 0; mt < 4; mt++)
#pragma unroll
        for (int nt = 0; nt < 4; nt++) {
            int colseg = wn + nt * 8 + ((lc & 2) << 1);
            float4 bv = *(const float4*)&be3[colseg];
            bool ev = (lc & 1) == 0;
            float s0 = ev ? d[mt][nt][2] : d[mt][nt][0];
            float s1 = ev ? d[mt][nt][3] : d[mt][nt][1];
            float r0 = __uint_as_float(__shfl_xor_sync(0xffffffffu, __float_as_uint(s0), 1));
            float r1 = __uint_as_float(__shfl_xor_sync(0xffffffffu, __float_as_uint(s1), 1));
            int e0 = wm + mt * 16 + lr;
            if (ev) {
                int tgt = s_col[e0];
                red_add_f4(&g_agg[(size_t)tgt * H + colseg],
                           d[mt][nt][0] + bv.x, d[mt][nt][1] + bv.y,
                           r0 + bv.z, r1 + bv.w);
            } else {
                int tgt = s_col[e0 + 8];
                red_add_f4(&g_agg[(size_t)tgt * H + colseg],
                           r0 + bv.x, r1 + bv.y,
                           d[mt][nt][2] + bv.z, d[mt][nt][3] + bv.w);
            }
        }
}

// ---------------------------------------------------------------- node MLP: inline agg cvt + zero
__global__ __launch_bounds__(256, 2)
void node_kernel(int layer,
                 const float* __restrict__ bn1, const float* __restrict__ bn2,
                 const float* __restrict__ bn3,
                 const float* __restrict__ lng, const float* __restrict__ lnb,
                 float* __restrict__ out) {
    extern __shared__ __align__(16) unsigned smem_u[];
    unsigned* sActs = smem_u + NACTS_OFF / 4;
    float* sLN = (float*)(smem_u + NLN_OFF / 4);

    unsigned sbase;
    asm("{ .reg .u64 t; cvta.to.shared.u64 t, %1; cvt.u32.u64 %0, t; }"
        : "=r"(sbase) : "l"(smem_u));
    const unsigned actsB = sbase + NACTS_OFF;
    const unsigned abufB[2] = {sbase + NABUF0_OFF, sbase + NABUF1_OFF};
    const unsigned bbufB[2] = {sbase + NBBUF0_OFF, sbase + NBBUF1_OFF};
    const unsigned abufOff[2] = {NABUF0_OFF, NABUF1_OFF};

    const __nv_bfloat16* W1 = &g_Wn1b[(size_t)layer * KN * H];
    const __nv_bfloat16* W2 = &g_Wn2b[(size_t)layer * H * H];
    const __nv_bfloat16* W3 = &g_Wn3b[(size_t)layer * H * H];

    int tid = threadIdx.x;
    int nb = blockIdx.x * BM;

    int warp = tid >> 5, lane = tid & 31;
    int lr = lane >> 2, lc = lane & 3;
    int wm = (warp & 1) * 64;
    int wn = (warp >> 1) * 32;

    int rA = tid >> 1, halfA = tid & 1;
    int rB = tid >> 3;
    int cB = (tid & 7) * 16;
    int nodeA = nb + rA; if (nodeA >= N_NODES) nodeA = N_NODES - 1;

    float d[4][4][4];
#pragma unroll
    for (int mt = 0; mt < 4; mt++)
#pragma unroll
        for (int nt = 0; nt < 4; nt++)
#pragma unroll
            for (int i = 0; i < 4; i++) d[mt][nt][i] = 0.f;

    auto issueA = [&](int ch, int p) {
        if (ch < 4) {
            cp16x2(abufB[p] + rA * 80 + halfA * 32,
                   &g_hb[(size_t)nodeA * H + ch * 32 + halfA * 16]);
        } else {
            // inline fp32 agg -> bf16 staging (replaces cvt_agg kernel; identical math)
            const float4* s = (const float4*)&g_agg[(size_t)nodeA * H + (ch - 4) * 32 + halfA * 16];
            float4 v0 = s[0], v1 = s[1], v2 = s[2], v3 = s[3];
            uint4 o0, o1;
            o0.x = pack_bf2(v0.x, v0.y); o0.y = pack_bf2(v0.z, v0.w);
            o0.z = pack_bf2(v1.x, v1.y); o0.w = pack_bf2(v1.z, v1.w);
            o1.x = pack_bf2(v2.x, v2.y); o1.y = pack_bf2(v2.z, v2.w);
            o1.z = pack_bf2(v3.x, v3.y); o1.w = pack_bf2(v3.z, v3.w);
            char* dst = (char*)smem_u + abufOff[p] + rA * 80 + halfA * 32;
            *(uint4*)dst = o0;
            *(uint4*)(dst + 16) = o1;
        }
    };
    auto issueB = [&](const __nv_bfloat16* Wb, int ch, int p) {
        cp16x2(bbufB[p] + rB * 272 + cB * 2,
               &Wb[(size_t)(ch * 32 + rB) * H + cB]);
    };

    issueA(0, 0);
    issueB(W1, 0, 0);
    CP_COMMIT;

    for (int ch = 0; ch < 8; ch++) {
        int p = ch & 1;
        if (ch < 7) {
            int p1 = (ch + 1) & 1;
            issueA(ch + 1, p1);
            issueB(W1, ch + 1, p1);
            CP_COMMIT;
            CP_WAIT1;
        } else {
            CP_WAIT0;
        }
        __syncthreads();
#pragma unroll
        for (int k16 = 0; k16 < 2; k16++) {
            int k0 = k16 * 16;
            unsigned a[4][4], b[4][2];
#pragma unroll
            for (int mt = 0; mt < 4; mt++)
                ldsm_x4(a[mt][0], a[mt][1], a[mt][2], a[mt][3],
                        abufB[p] + (wm + mt * 16 + (lane & 15)) * 80
                                 + (k0 + ((lane >> 4) << 3)) * 2);
#pragma unroll
            for (int np = 0; np < 2; np++)
                ldsm_x4t(b[2 * np][0], b[2 * np][1], b[2 * np + 1][0], b[2 * np + 1][1],
                         bbufB[p] + (k0 + (lane & 7) + (lane & 8)) * 272
                                  + (wn + np * 16 + ((lane >> 4) << 3)) * 2);
#pragma unroll
            for (int mt = 0; mt < 4; mt++)
#pragma unroll
                for (int nt = 0; nt < 4; nt++) mma_bf16(d[mt][nt], a[mt], b[nt]);
        }
        __syncthreads();
    }

    issueB(W2, 0, 0);
    CP_COMMIT;

#pragma unroll
    for (int mt = 0; mt < 4; mt++)
#pragma unroll
        for (int nt = 0; nt < 4; nt++) {
            int row = wm + mt * 16 + lr;
            int col = wn + nt * 8 + 2 * lc;
            float2 bv = *(const float2*)&bn1[col];
            sActs[(row * 136 + col) >> 1] =
                pack_bf2(fmaxf(d[mt][nt][0] + bv.x, 0.f), fmaxf(d[mt][nt][1] + bv.y, 0.f));
            sActs[((row + 8) * 136 + col) >> 1] =
                pack_bf2(fmaxf(d[mt][nt][2] + bv.x, 0.f), fmaxf(d[mt][nt][3] + bv.y, 0.f));
        }

#pragma unroll
    for (int mt = 0; mt < 4; mt++)
#pragma unroll
        for (int nt = 0; nt < 4; nt++)
#pragma unroll
            for (int i = 0; i < 4; i++) d[mt][nt][i] = 0.f;

    for (int ch = 0; ch < 4; ch++) {
        int p = ch & 1;
        if (ch < 3) {
            issueB(W2, ch + 1, (ch + 1) & 1);
            CP_COMMIT;
            CP_WAIT1;
        } else {
            CP_WAIT0;
        }
        __syncthreads();
#pragma unroll
        for (int k16 = 0; k16 < 2; k16++) {
            int kg = ch * 32 + k16 * 16;
            int k0 = k16 * 16;
            unsigned a[4][4], b[4][2];
#pragma unroll
            for (int mt = 0; mt < 4; mt++)
                ldsm_x4(a[mt][0], a[mt][1], a[mt][2], a[mt][3],
                        actsB + (wm + mt * 16 + (lane & 15)) * 272
                              + (kg + ((lane >> 4) << 3)) * 2);
#pragma unroll
            for (int np = 0; np < 2; np++)
                ldsm_x4t(b[2 * np][0], b[2 * np][1], b[2 * np + 1][0], b[2 * np + 1][1],
                         bbufB[p] + (k0 + (lane & 7) + (lane & 8)) * 272
                                  + (wn + np * 16 + ((lane >> 4) << 3)) * 2);
#pragma unroll
            for (int mt = 0; mt < 4; mt++)
#pragma unroll
                for (int nt = 0; nt < 4; nt++) mma_bf16(d[mt][nt], a[mt], b[nt]);
        }
        __syncthreads();
    }

    issueB(W3, 0, 0);
    CP_COMMIT;

#pragma unroll
    for (int mt = 0; mt < 4; mt++)
#pragma unroll
        for (int nt = 0; nt < 4; nt++) {
            int row = wm + mt * 16 + lr;
            int col = wn + nt * 8 + 2 * lc;
            float2 bv = *(const float2*)&bn2[col];
            sActs[(row * 136 + col) >> 1] =
                pack_bf2(fmaxf(d[mt][nt][0] + bv.x, 0.f), fmaxf(d[mt][nt][1] + bv.y, 0.f));
            sActs[((row + 8) * 136 + col) >> 1] =
                pack_bf2(fmaxf(d[mt][nt][2] + bv.x, 0.f), fmaxf(d[mt][nt][3] + bv.y, 0.f));
        }

#pragma unroll
    for (int mt = 0; mt < 4; mt++)
#pragma unroll
        for (int nt = 0; nt < 4; nt++)
#pragma unroll
            for (int i = 0; i < 4; i++) d[mt][nt][i] = 0.f;

    for (int ch = 0; ch < 4; ch++) {
        int p = ch & 1;
        if (ch < 3) {
            issueB(W3, ch + 1, (ch + 1) & 1);
            CP_COMMIT;
            CP_WAIT1;
        } else {
            CP_WAIT0;
        }
        __syncthreads();
#pragma unroll
        for (int k16 = 0; k16 < 2; k16++) {
            int kg = ch * 32 + k16 * 16;
            int k0 = k16 * 16;
            unsigned a[4][4], b[4][2];
#pragma unroll
            for (int mt = 0; mt < 4; mt++)
                ldsm_x4(a[mt][0], a[mt][1], a[mt][2], a[mt][3],
                        actsB + (wm + mt * 16 + (lane & 15)) * 272
                              + (kg + ((lane >> 4) << 3)) * 2);
#pragma unroll
            for (int np = 0; np < 2; np++)
                ldsm_x4t(b[2 * np][0], b[2 * np][1], b[2 * np + 1][0], b[2 * np + 1][1],
                         bbufB[p] + (k0 + (lane & 7) + (lane & 8)) * 272
                                  + (wn + np * 16 + ((lane >> 4) << 3)) * 2);
#pragma unroll
            for (int mt = 0; mt < 4; mt++)
#pragma unroll
                for (int nt = 0; nt < 4; nt++) mma_bf16(d[mt][nt], a[mt], b[nt]);
        }
        __syncthreads();
    }

#pragma unroll
    for (int mt = 0; mt < 4; mt++)
#pragma unroll
        for (int nt = 0; nt < 4; nt++) {
            int row = wm + mt * 16 + lr;
            int col = wn + nt * 8 + 2 * lc;
            float2 bv = *(const float2*)&bn3[col];
            int n0 = nb + row, n1 = nb + row + 8;
            float2 h0 = make_float2(0.f, 0.f), h1 = make_float2(0.f, 0.f);
            if (n0 < N_NODES) h0 = *(const float2*)&g_h[n0 * H + col];
            if (n1 < N_NODES) h1 = *(const float2*)&g_h[n1 * H + col];
            *(float2*)&sLN[row * 132 + col] =
                make_float2(h0.x + d[mt][nt][0] + bv.x, h0.y + d[mt][nt][1] + bv.y);
            *(float2*)&sLN[(row + 8) * 132 + col] =
                make_float2(h1.x + d[mt][nt][2] + bv.x, h1.y + d[mt][nt][3] + bv.y);
        }
    __syncthreads();

    // LayerNorm + write out + bf16 mirror + zero g_agg for next layer
    {
        for (int r = warp * 16; r < warp * 16 + 16; r++) {
            int node = nb + r;
            float v0 = sLN[r * 132 + lane];
            float v1 = sLN[r * 132 + lane + 32];
            float v2 = sLN[r * 132 + lane + 64];
            float v3 = sLN[r * 132 + lane + 96];
            float s = v0 + v1 + v2 + v3;
            float q = v0 * v0 + v1 * v1 + v2 * v2 + v3 * v3;
#pragma unroll
            for (int off = 16; off > 0; off >>= 1) {
                s += __shfl_xor_sync(0xffffffffu, s, off);
                q += __shfl_xor_sync(0xffffffffu, q, off);
            }
            float mean = s * (1.f / 128.f);
            float var = q * (1.f / 128.f) - mean * mean;
            float rstd = rsqrtf(var + 1e-5f);
            if (node < N_NODES) {
                float o0 = (v0 - mean) * rstd * lng[lane]      + lnb[lane];
                float o1 = (v1 - mean) * rstd * lng[lane + 32] + lnb[lane + 32];
                float o2 = (v2 - mean) * rstd * lng[lane + 64] + lnb[lane + 64];
                float o3 = (v3 - mean) * rstd * lng[lane + 96] + lnb[lane + 96];
                out[node * H + lane]      = o0;
                out[node * H + lane + 32] = o1;
                out[node * H + lane + 64] = o2;
                out[node * H + lane + 96] = o3;
                g_hb[node * H + lane]      = __float2bfloat16(o0);
                g_hb[node * H + lane + 32] = __float2bfloat16(o1);
                g_hb[node * H + lane + 64] = __float2bfloat16(o2);
                g_hb[node * H + lane + 96] = __float2bfloat16(o3);
                g_agg[node * H + lane]      = 0.f;
                g_agg[node * H + lane + 32] = 0.f;
                g_agg[node * H + lane + 64] = 0.f;
                g_agg[node * H + lane + 96] = 0.f;
            }
        }
    }
}

// ----------------------------------------------------------------
extern "C" void kernel_launch(void* const* d_in, const int* in_sizes, int n_in,
                              void* d_out, int out_size) {
    const float* x    = (const float*)d_in[0];
    const float* pos  = (const float*)d_in[1];
    const int*   ei   = (const int*)d_in[2];
    const float* W_in = (const float*)d_in[3];
    const float* b_in = (const float*)d_in[4];
    const float* We1  = (const float*)d_in[5];
    const float* be1  = (const float*)d_in[6];
    const float* We2  = (const float*)d_in[7];
    const float* be2  = (const float*)d_in[8];
    const float* We3  = (const float*)d_in[9];
    const float* be3  = (const float*)d_in[10];
    const float* Wn1  = (const float*)d_in[11];
    const float* bn1  = (const float*)d_in[12];
    const float* Wn2  = (const float*)d_in[13];
    const float* bn2  = (const float*)d_in[14];
    const float* Wn3  = (const float*)d_in[15];
    const float* bn3  = (const float*)d_in[16];
    const float* ln_g = (const float*)d_in[17];
    const float* ln_b = (const float*)d_in[18];

    const int* rowIdx = ei;
    const int* colIdx = ei + N_EDGES;

    cudaFuncSetAttribute(edge_kernel, cudaFuncAttributeMaxDynamicSharedMemorySize, SMEM_EDGE);
    cudaFuncSetAttribute(node_kernel, cudaFuncAttributeMaxDynamicSharedMemorySize, SMEM_NODE);

    float* hptr = nullptr;
    cudaGetSymbolAddress((void**)&hptr, g_h);

    int prep_total = LAYERS * KE_PAD * H + 2 * LAYERS * H * H
                   + LAYERS * KN * H + 2 * LAYERS * H * H;
    // launch order keeps edge_kernel at process-launch #4 (ncu capture slot)
    prep_weights<<<(prep_total + 255) / 256, 256>>>(We1, We2, We3, Wn1, Wn2, Wn3);
    embed_kernel<<<(N_NODES * H + 255) / 256, 256>>>(x, W_in, b_in);  // also zeroes g_agg
    ea_kernel<<<(N_EDGES + 255) / 256, 256>>>(pos, rowIdx, colIdx);

    int edge_blocks = N_EDGES / BM;
    int node_blocks = (N_NODES + BM - 1) / BM;

    for (int l = 0; l < LAYERS; l++) {
        edge_kernel<<<edge_blocks, 256, SMEM_EDGE>>>(
            l, be1 + l * H, be2 + l * H, be3 + l * H, rowIdx, colIdx);
        float* outp = (l == LAYERS - 1) ? (float*)d_out : hptr;
        node_kernel<<<node_blocks, 256, SMEM_NODE>>>(
            l, bn1 + l * H, bn2 + l * H, bn3 + l * H,
            ln_g + l * H, ln_b + l * H, outp);
    }
}

// round 17
// speedup vs baseline: 1.4707x; 1.0055x over previous
#include <cuda_runtime.h>
#include <cuda_bf16.h>
#include <cstdint>
#include <math.h>

#define N_NODES 50000
#define N_EDGES 800000
#define H 128
#define LAYERS 4
#define KE 263
#define KN 256
#define BM 128
#define KE_PAD 288

// edge + node shared smem layout (bytes), total 73728
#define ACTS_OFF  1024
#define ABUF0_OFF 35840
#define ABUF1_OFF 46080
#define BBUF0_OFF 56320
#define BBUF1_OFF 65024
#define SMEM_EDGE 73728

#define NACTS_OFF  1024
#define NABUF0_OFF 35840
#define NABUF1_OFF 46080
#define NBBUF0_OFF 56320
#define NBBUF1_OFF 65024
#define SMEM_NODE  73728
#define NLN_OFF    1024

__device__ float g_h[N_NODES * H];
__device__ float g_agg[N_NODES * H];
__device__ float g_ea[N_EDGES * 4];
__device__ __nv_bfloat16 g_hb[N_NODES * H];
__device__ __nv_bfloat16 g_We1b[LAYERS * KE_PAD * H];
__device__ __nv_bfloat16 g_We2b[LAYERS * H * H];
__device__ __nv_bfloat16 g_We3b[LAYERS * H * H];
__device__ __nv_bfloat16 g_Wn1b[LAYERS * KN * H];
__device__ __nv_bfloat16 g_Wn2b[LAYERS * H * H];
__device__ __nv_bfloat16 g_Wn3b[LAYERS * H * H];

#define CP_COMMIT asm volatile("cp.async.commit_group;" ::: "memory")
#define CP_WAIT1  asm volatile("cp.async.wait_group 1;" ::: "memory")
#define CP_WAIT0  asm volatile("cp.async.wait_group 0;" ::: "memory")

__device__ __forceinline__ void cp16x2(unsigned dst, const void* src) {
    asm volatile("cp.async.cg.shared.global [%0], [%1], 16;\n\t"
                 "cp.async.cg.shared.global [%2], [%3], 16;"
                 :: "r"(dst), "l"(src), "r"(dst + 16), "l"((const char*)src + 16) : "memory");
}
__device__ __forceinline__ void red_add_f4(float* p, float a, float b, float c, float d) {
    asm volatile("red.global.add.v4.f32 [%0], {%1,%2,%3,%4};"
                 :: "l"(p), "f"(a), "f"(b), "f"(c), "f"(d) : "memory");
}
__device__ __forceinline__ unsigned pack_bf2(float lo, float hi) {
    __nv_bfloat162 v = __floats2bfloat162_rn(lo, hi);
    return *(unsigned*)&v;
}
__device__ __forceinline__ void ldsm_x4(unsigned& r0, unsigned& r1, unsigned& r2, unsigned& r3,
                                        unsigned addr) {
    asm volatile("ldmatrix.sync.aligned.m8n8.x4.shared.b16 {%0,%1,%2,%3}, [%4];"
                 : "=r"(r0), "=r"(r1), "=r"(r2), "=r"(r3) : "r"(addr));
}
__device__ __forceinline__ void ldsm_x4t(unsigned& r0, unsigned& r1, unsigned& r2, unsigned& r3,
                                         unsigned addr) {
    asm volatile("ldmatrix.sync.aligned.m8n8.x4.trans.shared.b16 {%0,%1,%2,%3}, [%4];"
                 : "=r"(r0), "=r"(r1), "=r"(r2), "=r"(r3) : "r"(addr));
}
__device__ __forceinline__ void mma_bf16(float d[4], const unsigned a[4], const unsigned b[2]) {
    asm volatile("mma.sync.aligned.m16n8k16.row.col.f32.bf16.bf16.f32 "
                 "{%0,%1,%2,%3}, {%4,%5,%6,%7}, {%8,%9}, {%0,%1,%2,%3};"
                 : "+f"(d[0]), "+f"(d[1]), "+f"(d[2]), "+f"(d[3])
                 : "r"(a[0]), "r"(a[1]), "r"(a[2]), "r"(a[3]), "r"(b[0]), "r"(b[1]));
}

// ---------------------------------------------------------------- weight prep (fp32 -> bf16)
__global__ void prep_weights(const float* __restrict__ We1,
                             const float* __restrict__ We2,
                             const float* __restrict__ We3,
                             const float* __restrict__ Wn1,
                             const float* __restrict__ Wn2,
                             const float* __restrict__ Wn3) {
    int id = blockIdx.x * blockDim.x + threadIdx.x;
    const int n1 = LAYERS * KE_PAD * H;
    const int n2 = LAYERS * H * H;
    const int n3 = LAYERS * KN * H;
    if (id < n1) {
        int l = id / (KE_PAD * H);
        int rem = id % (KE_PAD * H);
        int r = rem / H, c = rem % H;
        float v = (r < KE) ? We1[((size_t)l * KE + r) * H + c] : 0.f;
        g_We1b[id] = __float2bfloat16(v);
    } else if (id < n1 + n2) {
        g_We2b[id - n1] = __float2bfloat16(We2[id - n1]);
    } else if (id < n1 + 2 * n2) {
        g_We3b[id - n1 - n2] = __float2bfloat16(We3[id - n1 - n2]);
    } else if (id < n1 + 2 * n2 + n3) {
        int k = id - n1 - 2 * n2;
        g_Wn1b[k] = __float2bfloat16(Wn1[k]);
    } else if (id < n1 + 2 * n2 + n3 + n2) {
        int k = id - n1 - 2 * n2 - n3;
        g_Wn2b[k] = __float2bfloat16(Wn2[k]);
    } else if (id < n1 + 2 * n2 + n3 + 2 * n2) {
        int k = id - n1 - 2 * n2 - n3 - n2;
        g_Wn3b[k] = __float2bfloat16(Wn3[k]);
    }
}

// ---------------------------------------------------------------- embed (+ zero g_agg)
__global__ void embed_kernel(const float* __restrict__ x,
                             const float* __restrict__ W,
                             const float* __restrict__ b) {
    int gid = blockIdx.x * blockDim.x + threadIdx.x;
    if (gid >= N_NODES * H) return;
    int i = gid >> 7;
    int j = gid & (H - 1);
    const float* xr = x + i * 16;
    float acc = b[j];
#pragma unroll
    for (int k = 0; k < 16; k++) acc += xr[k] * W[k * H + j];
    g_h[gid] = acc;
    g_hb[gid] = __float2bfloat16(acc);
    g_agg[gid] = 0.f;
}

__global__ void ea_kernel(const float* __restrict__ pos,
                          const int* __restrict__ rowIdx,
                          const int* __restrict__ colIdx) {
    int e = blockIdx.x * blockDim.x + threadIdx.x;
    if (e >= N_EDGES) return;
    int r = rowIdx[e], c = colIdx[e];
    float dx = pos[c * 3 + 0] - pos[r * 3 + 0];
    float dy = pos[c * 3 + 1] - pos[r * 3 + 1];
    float dz = pos[c * 3 + 2] - pos[r * 3 + 2];
    float d = sqrtf(dx * dx + dy * dy + dz * dz);
    *(float4*)&g_ea[e * 4] = make_float4(dx, dy, dz, d);
}

// ---------------------------------------------------------------- fused edge MLP (R15 pipeline)
__global__ __launch_bounds__(256, 2)
void edge_kernel(int layer,
                 const float* __restrict__ be1, const float* __restrict__ be2,
                 const float* __restrict__ be3,
                 const int* __restrict__ rowIdx, const int* __restrict__ colIdx) {
    extern __shared__ __align__(16) unsigned smem_u[];
    int* s_col = (int*)smem_u;
    int* s_row = s_col + 128;
    unsigned* sActs = smem_u + ACTS_OFF / 4;
    unsigned* sA8 = smem_u + ACTS_OFF / 4;    // ea-tail tile aliases acts start

    unsigned sbase;
    asm("{ .reg .u64 t; cvta.to.shared.u64 t, %1; cvt.u32.u64 %0, t; }"
        : "=r"(sbase) : "l"(smem_u));
    const unsigned actsB = sbase + ACTS_OFF;
    const unsigned a8B = actsB;
    const unsigned abufB[2] = {sbase + ABUF0_OFF, sbase + ABUF1_OFF};
    const unsigned bbufB[2] = {sbase + BBUF0_OFF, sbase + BBUF1_OFF};

    const __nv_bfloat16* W1 = &g_We1b[(size_t)layer * KE_PAD * H];
    const __nv_bfloat16* W2 = &g_We2b[(size_t)layer * H * H];
    const __nv_bfloat16* W3 = &g_We3b[(size_t)layer * H * H];

    int tid = threadIdx.x;
    int eb = blockIdx.x * BM;

    if (tid < 128) s_col[tid] = colIdx[eb + tid];
    else           s_row[tid - 128] = rowIdx[eb + tid - 128];
    __syncthreads();

    int warp = tid >> 5, lane = tid & 31;
    int lr = lane >> 2, lc = lane & 3;
    int wm = (warp & 1) * 64;
    int wn = (warp >> 1) * 32;

    int rA = tid >> 1, halfA = tid & 1;
    int rB = tid >> 3;
    int cB = (tid & 7) * 16;

    if (tid < 128) {
        int r = tid;
        float4 ea = *(const float4*)&g_ea[(eb + r) * 4];
        int ci = s_col[r] * H, ri = s_row[r] * H;
        float rm0 = g_h[ci + 3] - g_h[ri + 3];
        float rm1 = g_h[ci + 4] - g_h[ri + 4];
        float rm2 = g_h[ci + 5] - g_h[ri + 5];
        unsigned* dst = &sA8[r * 12];
        dst[0] = pack_bf2(ea.x, ea.y);
        dst[1] = pack_bf2(ea.z, ea.w);
        dst[2] = pack_bf2(rm0, rm1);
        dst[3] = pack_bf2(rm2, 0.f);
        dst[4] = 0u; dst[5] = 0u; dst[6] = 0u; dst[7] = 0u;
    }

    float d[4][4][4];
#pragma unroll
    for (int mt = 0; mt < 4; mt++)
#pragma unroll
        for (int nt = 0; nt < 4; nt++)
#pragma unroll
            for (int i = 0; i < 4; i++) d[mt][nt][i] = 0.f;

    auto issueA = [&](int ch, int p) {
        int node = (ch < 4) ? s_col[rA] : s_row[rA];
        int kbase = (ch & 3) * 32;
        cp16x2(abufB[p] + rA * 80 + halfA * 32,
               &g_hb[(size_t)node * H + kbase + halfA * 16]);
    };
    auto issueB = [&](const __nv_bfloat16* Wb, int ch, int p) {
        cp16x2(bbufB[p] + rB * 272 + cB * 2,
               &Wb[(size_t)(ch * 32 + rB) * H + cB]);
    };

    // ===== GEMM1: K = 288 padded (9 chunks, double-buffered, wait->barrier->read)
    issueA(0, 0);
    issueB(W1, 0, 0);
    CP_COMMIT;

    for (int ch = 0; ch <= 8; ch++) {
        int p = ch & 1;
        if (ch < 8) {
            int p1 = (ch + 1) & 1;
            if (ch + 1 < 8) issueA(ch + 1, p1);
            issueB(W1, ch + 1, p1);
            CP_COMMIT;
            CP_WAIT1;
        } else {
            CP_WAIT0;
        }
        __syncthreads();
        int nk16 = (ch < 8) ? 2 : 1;
        for (int k16 = 0; k16 < nk16; k16++) {
            int k0 = k16 * 16;
            unsigned a[4][4], b[4][2];
#pragma unroll
            for (int np = 0; np < 2; np++)
                ldsm_x4t(b[2 * np][0], b[2 * np][1], b[2 * np + 1][0], b[2 * np + 1][1],
                         bbufB[p] + (k0 + (lane & 7) + (lane & 8)) * 272
                                  + (wn + np * 16 + ((lane >> 4) << 3)) * 2);
            if (ch < 8) {
#pragma unroll
                for (int mt = 0; mt < 4; mt++)
                    ldsm_x4(a[mt][0], a[mt][1], a[mt][2], a[mt][3],
                            abufB[p] + (wm + mt * 16 + (lane & 15)) * 80
                                     + (k0 + ((lane >> 4) << 3)) * 2);
            } else {
#pragma unroll
                for (int mt = 0; mt < 4; mt++)
                    ldsm_x4(a[mt][0], a[mt][1], a[mt][2], a[mt][3],
                            a8B + (wm + mt * 16 + (lane & 15)) * 48
                                + ((lane >> 4) << 3) * 2);
            }
#pragma unroll
            for (int mt = 0; mt < 4; mt++)
#pragma unroll
                for (int nt = 0; nt < 4; nt++) mma_bf16(d[mt][nt], a[mt], b[nt]);
        }
        __syncthreads();
    }

    issueB(W2, 0, 0);
    CP_COMMIT;

    // epilogue1: bias + relu -> acts
#pragma unroll
    for (int mt = 0; mt < 4; mt++)
#pragma unroll
        for (int nt = 0; nt < 4; nt++) {
            int row = wm + mt * 16 + lr;
            int col = wn + nt * 8 + 2 * lc;
            float2 bv = *(const float2*)&be1[col];
            sActs[(row * 136 + col) >> 1] =
                pack_bf2(fmaxf(d[mt][nt][0] + bv.x, 0.f), fmaxf(d[mt][nt][1] + bv.y, 0.f));
            sActs[((row + 8) * 136 + col) >> 1] =
                pack_bf2(fmaxf(d[mt][nt][2] + bv.x, 0.f), fmaxf(d[mt][nt][3] + bv.y, 0.f));
        }

    // ===== GEMM2
#pragma unroll
    for (int mt = 0; mt < 4; mt++)
#pragma unroll
        for (int nt = 0; nt < 4; nt++)
#pragma unroll
            for (int i = 0; i < 4; i++) d[mt][nt][i] = 0.f;

    for (int ch = 0; ch < 4; ch++) {
        int p = ch & 1;
        if (ch < 3) {
            issueB(W2, ch + 1, (ch + 1) & 1);
            CP_COMMIT;
            CP_WAIT1;
        } else {
            CP_WAIT0;
        }
        __syncthreads();
#pragma unroll
        for (int k16 = 0; k16 < 2; k16++) {
            int kg = ch * 32 + k16 * 16;
            int k0 = k16 * 16;
            unsigned a[4][4], b[4][2];
#pragma unroll
            for (int np = 0; np < 2; np++)
                ldsm_x4t(b[2 * np][0], b[2 * np][1], b[2 * np + 1][0], b[2 * np + 1][1],
                         bbufB[p] + (k0 + (lane & 7) + (lane & 8)) * 272
                                  + (wn + np * 16 + ((lane >> 4) << 3)) * 2);
#pragma unroll
            for (int mt = 0; mt < 4; mt++)
                ldsm_x4(a[mt][0], a[mt][1], a[mt][2], a[mt][3],
                        actsB + (wm + mt * 16 + (lane & 15)) * 272
                              + (kg + ((lane >> 4) << 3)) * 2);
#pragma unroll
            for (int mt = 0; mt < 4; mt++)
#pragma unroll
                for (int nt = 0; nt < 4; nt++) mma_bf16(d[mt][nt], a[mt], b[nt]);
        }
        __syncthreads();
    }

    issueB(W3, 0, 0);
    CP_COMMIT;

#pragma unroll
    for (int mt = 0; mt < 4; mt++)
#pragma unroll
        for (int nt = 0; nt < 4; nt++) {
            int row = wm + mt * 16 + lr;
            int col = wn + nt * 8 + 2 * lc;
            float2 bv = *(const float2*)&be2[col];
            sActs[(row * 136 + col) >> 1] =
                pack_bf2(fmaxf(d[mt][nt][0] + bv.x, 0.f), fmaxf(d[mt][nt][1] + bv.y, 0.f));
            sActs[((row + 8) * 136 + col) >> 1] =
                pack_bf2(fmaxf(d[mt][nt][2] + bv.x, 0.f), fmaxf(d[mt][nt][3] + bv.y, 0.f));
        }

    // ===== GEMM3
#pragma unroll
    for (int mt = 0; mt < 4; mt++)
#pragma unroll
        for (int nt = 0; nt < 4; nt++)
#pragma unroll
            for (int i = 0; i < 4; i++) d[mt][nt][i] = 0.f;

    for (int ch = 0; ch < 4; ch++) {
        int p = ch & 1;
        if (ch < 3) {
            issueB(W3, ch + 1, (ch + 1) & 1);
            CP_COMMIT;
            CP_WAIT1;
        } else {
            CP_WAIT0;
        }
        __syncthreads();
#pragma unroll
        for (int k16 = 0; k16 < 2; k16++) {
            int kg = ch * 32 + k16 * 16;
            int k0 = k16 * 16;
            unsigned a[4][4], b[4][2];
#pragma unroll
            for (int np = 0; np < 2; np++)
                ldsm_x4t(b[2 * np][0], b[2 * np][1], b[2 * np + 1][0], b[2 * np + 1][1],
                         bbufB[p] + (k0 + (lane & 7) + (lane & 8)) * 272
                                  + (wn + np * 16 + ((lane >> 4) << 3)) * 2);
#pragma unroll
            for (int mt = 0; mt < 4; mt++)
                ldsm_x4(a[mt][0], a[mt][1], a[mt][2], a[mt][3],
                        actsB + (wm + mt * 16 + (lane & 15)) * 272
                              + (kg + ((lane >> 4) << 3)) * 2);
#pragma unroll
            for (int mt = 0; mt < 4; mt++)
#pragma unroll
                for (int nt = 0; nt < 4; nt++) mma_bf16(d[mt][nt], a[mt], b[nt]);
        }
        __syncthreads();
    }

    // epilogue3: pair-shuffle v4 reds
#pragma unroll
    for (int mt = 0; mt < 4; mt++)
#pragma unroll
        for (int nt = 0; nt < 4; nt++) {
            int colseg = wn + nt * 8 + ((lc & 2) << 1);
            float4 bv = *(const float4*)&be3[colseg];
            bool ev = (lc & 1) == 0;
            float s0 = ev ? d[mt][nt][2] : d[mt][nt][0];
            float s1 = ev ? d[mt][nt][3] : d[mt][nt][1];
            float r0 = __uint_as_float(__shfl_xor_sync(0xffffffffu, __float_as_uint(s0), 1));
            float r1 = __uint_as_float(__shfl_xor_sync(0xffffffffu, __float_as_uint(s1), 1));
            int e0 = wm + mt * 16 + lr;
            if (ev) {
                int tgt = s_col[e0];
                red_add_f4(&g_agg[(size_t)tgt * H + colseg],
                           d[mt][nt][0] + bv.x, d[mt][nt][1] + bv.y,
                           r0 + bv.z, r1 + bv.w);
            } else {
                int tgt = s_col[e0 + 8];
                red_add_f4(&g_agg[(size_t)tgt * H + colseg],
                           r0 + bv.x, r1 + bv.y,
                           d[mt][nt][2] + bv.z, d[mt][nt][3] + bv.w);
            }
        }
}

// ---------------------------------------------------------------- node MLP: inline agg cvt + zero
__global__ __launch_bounds__(256, 2)
void node_kernel(int layer,
                 const float* __restrict__ bn1, const float* __restrict__ bn2,
                 const float* __restrict__ bn3,
                 const float* __restrict__ lng, const float* __restrict__ lnb,
                 float* __restrict__ out) {
    extern __shared__ __align__(16) unsigned smem_u[];
    unsigned* sActs = smem_u + NACTS_OFF / 4;
    float* sLN = (float*)(smem_u + NLN_OFF / 4);

    unsigned sbase;
    asm("{ .reg .u64 t; cvta.to.shared.u64 t, %1; cvt.u32.u64 %0, t; }"
        : "=r"(sbase) : "l"(smem_u));
    const unsigned actsB = sbase + NACTS_OFF;
    const unsigned abufB[2] = {sbase + NABUF0_OFF, sbase + NABUF1_OFF};
    const unsigned bbufB[2] = {sbase + NBBUF0_OFF, sbase + NBBUF1_OFF};
    const unsigned abufOff[2] = {NABUF0_OFF, NABUF1_OFF};

    const __nv_bfloat16* W1 = &g_Wn1b[(size_t)layer * KN * H];
    const __nv_bfloat16* W2 = &g_Wn2b[(size_t)layer * H * H];
    const __nv_bfloat16* W3 = &g_Wn3b[(size_t)layer * H * H];

    int tid = threadIdx.x;
    int nb = blockIdx.x * BM;

    int warp = tid >> 5, lane = tid & 31;
    int lr = lane >> 2, lc = lane & 3;
    int wm = (warp & 1) * 64;
    int wn = (warp >> 1) * 32;

    int rA = tid >> 1, halfA = tid & 1;
    int rB = tid >> 3;
    int cB = (tid & 7) * 16;
    int nodeA = nb + rA; if (nodeA >= N_NODES) nodeA = N_NODES - 1;

    float d[4][4][4];
#pragma unroll
    for (int mt = 0; mt < 4; mt++)
#pragma unroll
        for (int nt = 0; nt < 4; nt++)
#pragma unroll
            for (int i = 0; i < 4; i++) d[mt][nt][i] = 0.f;

    auto issueA = [&](int ch, int p) {
        if (ch < 4) {
            cp16x2(abufB[p] + rA * 80 + halfA * 32,
                   &g_hb[(size_t)nodeA * H + ch * 32 + halfA * 16]);
        } else {
            const float4* s = (const float4*)&g_agg[(size_t)nodeA * H + (ch - 4) * 32 + halfA * 16];
            float4 v0 = s[0], v1 = s[1], v2 = s[2], v3 = s[3];
            uint4 o0, o1;
            o0.x = pack_bf2(v0.x, v0.y); o0.y = pack_bf2(v0.z, v0.w);
            o0.z = pack_bf2(v1.x, v1.y); o0.w = pack_bf2(v1.z, v1.w);
            o1.x = pack_bf2(v2.x, v2.y); o1.y = pack_bf2(v2.z, v2.w);
            o1.z = pack_bf2(v3.x, v3.y); o1.w = pack_bf2(v3.z, v3.w);
            char* dst = (char*)smem_u + abufOff[p] + rA * 80 + halfA * 32;
            *(uint4*)dst = o0;
            *(uint4*)(dst + 16) = o1;
        }
    };
    auto issueB = [&](const __nv_bfloat16* Wb, int ch, int p) {
        cp16x2(bbufB[p] + rB * 272 + cB * 2,
               &Wb[(size_t)(ch * 32 + rB) * H + cB]);
    };

    issueA(0, 0);
    issueB(W1, 0, 0);
    CP_COMMIT;

    for (int ch = 0; ch < 8; ch++) {
        int p = ch & 1;
        if (ch < 7) {
            int p1 = (ch + 1) & 1;
            issueA(ch + 1, p1);
            issueB(W1, ch + 1, p1);
            CP_COMMIT;
            CP_WAIT1;
        } else {
            CP_WAIT0;
        }
        __syncthreads();
#pragma unroll
        for (int k16 = 0; k16 < 2; k16++) {
            int k0 = k16 * 16;
            unsigned a[4][4], b[4][2];
#pragma unroll
            for (int mt = 0; mt < 4; mt++)
                ldsm_x4(a[mt][0], a[mt][1], a[mt][2], a[mt][3],
                        abufB[p] + (wm + mt * 16 + (lane & 15)) * 80
                                 + (k0 + ((lane >> 4) << 3)) * 2);
#pragma unroll
            for (int np = 0; np < 2; np++)
                ldsm_x4t(b[2 * np][0], b[2 * np][1], b[2 * np + 1][0], b[2 * np + 1][1],
                         bbufB[p] + (k0 + (lane & 7) + (lane & 8)) * 272
                                  + (wn + np * 16 + ((lane >> 4) << 3)) * 2);
#pragma unroll
            for (int mt = 0; mt < 4; mt++)
#pragma unroll
                for (int nt = 0; nt < 4; nt++) mma_bf16(d[mt][nt], a[mt], b[nt]);
        }
        __syncthreads();
    }

    issueB(W2, 0, 0);
    CP_COMMIT;

#pragma unroll
    for (int mt = 0; mt < 4; mt++)
#pragma unroll
        for (int nt = 0; nt < 4; nt++) {
            int row = wm + mt * 16 + lr;
            int col = wn + nt * 8 + 2 * lc;
            float2 bv = *(const float2*)&bn1[col];
            sActs[(row * 136 + col) >> 1] =
                pack_bf2(fmaxf(d[mt][nt][0] + bv.x, 0.f), fmaxf(d[mt][nt][1] + bv.y, 0.f));
            sActs[((row + 8) * 136 + col) >> 1] =
                pack_bf2(fmaxf(d[mt][nt][2] + bv.x, 0.f), fmaxf(d[mt][nt][3] + bv.y, 0.f));
        }

#pragma unroll
    for (int mt = 0; mt < 4; mt++)
#pragma unroll
        for (int nt = 0; nt < 4; nt++)
#pragma unroll
            for (int i = 0; i < 4; i++) d[mt][nt][i] = 0.f;

    for (int ch = 0; ch < 4; ch++) {
        int p = ch & 1;
        if (ch < 3) {
            issueB(W2, ch + 1, (ch + 1) & 1);
            CP_COMMIT;
            CP_WAIT1;
        } else {
            CP_WAIT0;
        }
        __syncthreads();
#pragma unroll
        for (int k16 = 0; k16 < 2; k16++) {
            int kg = ch * 32 + k16 * 16;
            int k0 = k16 * 16;
            unsigned a[4][4], b[4][2];
#pragma unroll
            for (int mt = 0; mt < 4; mt++)
                ldsm_x4(a[mt][0], a[mt][1], a[mt][2], a[mt][3],
                        actsB + (wm + mt * 16 + (lane & 15)) * 272
                              + (kg + ((lane >> 4) << 3)) * 2);
#pragma unroll
            for (int np = 0; np < 2; np++)
                ldsm_x4t(b[2 * np][0], b[2 * np][1], b[2 * np + 1][0], b[2 * np + 1][1],
                         bbufB[p] + (k0 + (lane & 7) + (lane & 8)) * 272
                                  + (wn + np * 16 + ((lane >> 4) << 3)) * 2);
#pragma unroll
            for (int mt = 0; mt < 4; mt++)
#pragma unroll
                for (int nt = 0; nt < 4; nt++) mma_bf16(d[mt][nt], a[mt], b[nt]);
        }
        __syncthreads();
    }

    issueB(W3, 0, 0);
    CP_COMMIT;

#pragma unroll
    for (int mt = 0; mt < 4; mt++)
#pragma unroll
        for (int nt = 0; nt < 4; nt++) {
            int row = wm + mt * 16 + lr;
            int col = wn + nt * 8 + 2 * lc;
            float2 bv = *(const float2*)&bn2[col];
            sActs[(row * 136 + col) >> 1] =
                pack_bf2(fmaxf(d[mt][nt][0] + bv.x, 0.f), fmaxf(d[mt][nt][1] + bv.y, 0.f));
            sActs[((row + 8) * 136 + col) >> 1] =
                pack_bf2(fmaxf(d[mt][nt][2] + bv.x, 0.f), fmaxf(d[mt][nt][3] + bv.y, 0.f));
        }

#pragma unroll
    for (int mt = 0; mt < 4; mt++)
#pragma unroll
        for (int nt = 0; nt < 4; nt++)
#pragma unroll
            for (int i = 0; i < 4; i++) d[mt][nt][i] = 0.f;

    for (int ch = 0; ch < 4; ch++) {
        int p = ch & 1;
        if (ch < 3) {
            issueB(W3, ch + 1, (ch + 1) & 1);
            CP_COMMIT;
            CP_WAIT1;
        } else {
            CP_WAIT0;
        }
        __syncthreads();
#pragma unroll
        for (int k16 = 0; k16 < 2; k16++) {
            int kg = ch * 32 + k16 * 16;
            int k0 = k16 * 16;
            unsigned a[4][4], b[4][2];
#pragma unroll
            for (int mt = 0; mt < 4; mt++)
                ldsm_x4(a[mt][0], a[mt][1], a[mt][2], a[mt][3],
                        actsB + (wm + mt * 16 + (lane & 15)) * 272
                              + (kg + ((lane >> 4) << 3)) * 2);
#pragma unroll
            for (int np = 0; np < 2; np++)
                ldsm_x4t(b[2 * np][0], b[2 * np][1], b[2 * np + 1][0], b[2 * np + 1][1],
                         bbufB[p] + (k0 + (lane & 7) + (lane & 8)) * 272
                                  + (wn + np * 16 + ((lane >> 4) << 3)) * 2);
#pragma unroll
            for (int mt = 0; mt < 4; mt++)
#pragma unroll
                for (int nt = 0; nt < 4; nt++) mma_bf16(d[mt][nt], a[mt], b[nt]);
        }
        __syncthreads();
    }

#pragma unroll
    for (int mt = 0; mt < 4; mt++)
#pragma unroll
        for (int nt = 0; nt < 4; nt++) {
            int row = wm + mt * 16 + lr;
            int col = wn + nt * 8 + 2 * lc;
            float2 bv = *(const float2*)&bn3[col];
            int n0 = nb + row, n1 = nb + row + 8;
            float2 h0 = make_float2(0.f, 0.f), h1 = make_float2(0.f, 0.f);
            if (n0 < N_NODES) h0 = *(const float2*)&g_h[n0 * H + col];
            if (n1 < N_NODES) h1 = *(const float2*)&g_h[n1 * H + col];
            *(float2*)&sLN[row * 132 + col] =
                make_float2(h0.x + d[mt][nt][0] + bv.x, h0.y + d[mt][nt][1] + bv.y);
            *(float2*)&sLN[(row + 8) * 132 + col] =
                make_float2(h1.x + d[mt][nt][2] + bv.x, h1.y + d[mt][nt][3] + bv.y);
        }
    __syncthreads();

    // LayerNorm + write out + bf16 mirror + zero g_agg for next layer
    {
        for (int r = warp * 16; r < warp * 16 + 16; r++) {
            int node = nb + r;
            float v0 = sLN[r * 132 + lane];
            float v1 = sLN[r * 132 + lane + 32];
            float v2 = sLN[r * 132 + lane + 64];
            float v3 = sLN[r * 132 + lane + 96];
            float s = v0 + v1 + v2 + v3;
            float q = v0 * v0 + v1 * v1 + v2 * v2 + v3 * v3;
#pragma unroll
            for (int off = 16; off > 0; off >>= 1) {
                s += __shfl_xor_sync(0xffffffffu, s, off);
                q += __shfl_xor_sync(0xffffffffu, q, off);
            }
            float mean = s * (1.f / 128.f);
            float var = q * (1.f / 128.f) - mean * mean;
            float rstd = rsqrtf(var + 1e-5f);
            if (node < N_NODES) {
                float o0 = (v0 - mean) * rstd * lng[lane]      + lnb[lane];
                float o1 = (v1 - mean) * rstd * lng[lane + 32] + lnb[lane + 32];
                float o2 = (v2 - mean) * rstd * lng[lane + 64] + lnb[lane + 64];
                float o3 = (v3 - mean) * rstd * lng[lane + 96] + lnb[lane + 96];
                out[node * H + lane]      = o0;
                out[node * H + lane + 32] = o1;
                out[node * H + lane + 64] = o2;
                out[node * H + lane + 96] = o3;
                g_hb[node * H + lane]      = __float2bfloat16(o0);
                g_hb[node * H + lane + 32] = __float2bfloat16(o1);
                g_hb[node * H + lane + 64] = __float2bfloat16(o2);
                g_hb[node * H + lane + 96] = __float2bfloat16(o3);
                g_agg[node * H + lane]      = 0.f;
                g_agg[node * H + lane + 32] = 0.f;
                g_agg[node * H + lane + 64] = 0.f;
                g_agg[node * H + lane + 96] = 0.f;
            }
        }
    }
}

// ----------------------------------------------------------------
extern "C" void kernel_launch(void* const* d_in, const int* in_sizes, int n_in,
                              void* d_out, int out_size) {
    const float* x    = (const float*)d_in[0];
    const float* pos  = (const float*)d_in[1];
    const int*   ei   = (const int*)d_in[2];
    const float* W_in = (const float*)d_in[3];
    const float* b_in = (const float*)d_in[4];
    const float* We1  = (const float*)d_in[5];
    const float* be1  = (const float*)d_in[6];
    const float* We2  = (const float*)d_in[7];
    const float* be2  = (const float*)d_in[8];
    const float* We3  = (const float*)d_in[9];
    const float* be3  = (const float*)d_in[10];
    const float* Wn1  = (const float*)d_in[11];
    const float* bn1  = (const float*)d_in[12];
    const float* Wn2  = (const float*)d_in[13];
    const float* bn2  = (const float*)d_in[14];
    const float* Wn3  = (const float*)d_in[15];
    const float* bn3  = (const float*)d_in[16];
    const float* ln_g = (const float*)d_in[17];
    const float* ln_b = (const float*)d_in[18];

    const int* rowIdx = ei;
    const int* colIdx = ei + N_EDGES;

    cudaFuncSetAttribute(edge_kernel, cudaFuncAttributeMaxDynamicSharedMemorySize, SMEM_EDGE);
    cudaFuncSetAttribute(node_kernel, cudaFuncAttributeMaxDynamicSharedMemorySize, SMEM_NODE);

    float* hptr = nullptr;
    cudaGetSymbolAddress((void**)&hptr, g_h);

    int prep_total = LAYERS * KE_PAD * H + 2 * LAYERS * H * H
                   + LAYERS * KN * H + 2 * LAYERS * H * H;
    prep_weights<<<(prep_total + 255) / 256, 256>>>(We1, We2, We3, Wn1, Wn2, Wn3);
    embed_kernel<<<(N_NODES * H + 255) / 256, 256>>>(x, W_in, b_in);  // also zeroes g_agg
    ea_kernel<<<(N_EDGES + 255) / 256, 256>>>(pos, rowIdx, colIdx);

    int edge_blocks = N_EDGES / BM;
    int node_blocks = (N_NODES + BM - 1) / BM;

    for (int l = 0; l < LAYERS; l++) {
        edge_kernel<<<edge_blocks, 256, SMEM_EDGE>>>(
            l, be1 + l * H, be2 + l * H, be3 + l * H, rowIdx, colIdx);
        float* outp = (l == LAYERS - 1) ? (float*)d_out : hptr;
        node_kernel<<<node_blocks, 256, SMEM_NODE>>>(
            l, bn1 + l * H, bn2 + l * H, bn3 + l * H,
            ln_g + l * H, ln_b + l * H, outp);
    }
}